// round 1
// baseline (speedup 1.0000x reference)
#include <cuda_runtime.h>

// Fused NonLinearReadoutLayer, fp32 with packed f32x2 FFMA.
//
//   s = x[:, :128]; v[n,m,c] = x[n, 128 + m*3 + c]
//   h_s = s @ w1_s * INV            (N,256)
//   h_v[n,k,c] = sum_m v[n,m,c] w1_v[m,k] * INV
//   act = silu(h_s[:, :128]); gate = sigmoid(h_s[:, 128:])
//   out_s = act @ w2_s * INV        (N,16)
//   out_v[n,k,c] = sum_j (h_v[n,j,c]*gate[n,j]) w2_v[j,k] * INV
//   out[n] = [out_s (16) | out_v flattened k-major,c-minor (48)]

#define DIN     512
#define DOUT    64
#define MULD    128
#define TILE_M  128
#define THREADS 512

// smem pitches (floats)
#define PX 132   // sX  [k][n]  (also gated [n][k] later)
#define PA 132   // sACT [n][k]
#define PG 128   // sGATE [n][k]

// smem offsets (floats)
#define OFF_X    0
#define OFF_ACT  16896            // 128*132
#define OFF_GATE 33792            // + 128*132
#define OFF_W    50176            // + 128*128
#define OFF_W2S  52224            // + 2048 (weight chunk buf)
#define OFF_W2V  54272            // + 2048
#define SMEM_FLOATS 56320         // * 4 = 225280 bytes  (< 232448 limit)

typedef unsigned long long ull;

__device__ __forceinline__ ull pack2(float lo, float hi) {
    ull r; asm("mov.b64 %0, {%1, %2};" : "=l"(r) : "f"(lo), "f"(hi)); return r;
}
__device__ __forceinline__ void unpack2(ull v, float& lo, float& hi) {
    asm("mov.b64 {%0, %1}, %2;" : "=f"(lo), "=f"(hi) : "l"(v));
}
__device__ __forceinline__ void ffma2(ull& d, ull a, ull b) {
    asm("fma.rn.f32x2 %0, %1, %2, %0;" : "+l"(d) : "l"(a), "l"(b));
}
__device__ __forceinline__ float sigmoidf_(float x) {
    return __fdividef(1.0f, 1.0f + __expf(-x));
}

__global__ void __launch_bounds__(THREADS, 1)
nlro_kernel(const float* __restrict__ x,
            const float* __restrict__ w1s,
            const float* __restrict__ w1v,
            const float* __restrict__ w2s,
            const float* __restrict__ w2v,
            float* __restrict__ out, int N)
{
    extern __shared__ float sm[];
    float* sX    = sm + OFF_X;
    float* sACT  = sm + OFF_ACT;
    float* sGATE = sm + OFF_GATE;
    float* sW    = sm + OFF_W;
    float* sW2S  = sm + OFF_W2S;
    float* sW2V  = sm + OFF_W2V;

    const int  tid   = threadIdx.x;
    const long tile0 = (long)blockIdx.x * TILE_M;
    const float INV  = 0.08838834764831845f;   // 1/sqrt(128)

    // ---- stage w2_s, w2_v (2048 floats each) ----
    {
        float4 a = *(const float4*)&w2s[tid * 4];
        float4 b = *(const float4*)&w2v[tid * 4];
        *(float4*)&sW2S[tid * 4] = a;
        *(float4*)&sW2V[tid * 4] = b;
    }

    // ---- stage s-tile, transposed: sX[col][n] ----
    {
        int col = tid & 127, ng = tid >> 7;
        #pragma unroll 8
        for (int i = 0; i < 32; ++i) {
            int n = ng * 32 + i;
            long row = tile0 + n;
            float v = (row < N) ? x[row * DIN + col] : 0.0f;
            sX[col * PX + n] = v;
        }
    }
    // (visibility of staging covered by GEMM-internal barrier below)

    // ======== G1-s: Hs = S(128x128) @ W1s(128x256) ========
    // thread tile 8 rows x 8 cols; rg = warp id (broadcast a), cg = lane
    {
        const int rg = tid >> 5;        // 16 row groups * 8 rows
        const int cg = tid & 31;        // 32 col groups * 8 cols
        ull acc[8][4];
        #pragma unroll
        for (int r = 0; r < 8; ++r)
            #pragma unroll
            for (int c = 0; c < 4; ++c) acc[r][c] = 0ULL;

        const int lrow = tid >> 6;            // 0..7   (chunk = 8 k-rows x 256 cols)
        const int lcol = (tid * 4) & 255;
        float4 pre = *(const float4*)&w1s[lrow * 256 + lcol];

        for (int ch = 0; ch < 16; ++ch) {
            __syncthreads();                              // prev chunk fully consumed
            *(float4*)&sW[lrow * 256 + lcol] = pre;
            if (ch + 1 < 16)
                pre = *(const float4*)&w1s[((ch + 1) * 8 + lrow) * 256 + lcol];
            __syncthreads();                              // chunk (and staging) visible
            #pragma unroll
            for (int kk = 0; kk < 8; ++kk) {
                const int k = ch * 8 + kk;
                float4 a0 = *(const float4*)&sX[k * PX + rg * 8];
                float4 a1 = *(const float4*)&sX[k * PX + rg * 8 + 4];
                const ull* bp = (const ull*)&sW[kk * 256 + cg * 8];
                ull b0 = bp[0], b1 = bp[1], b2 = bp[2], b3 = bp[3];
                float a[8] = {a0.x, a0.y, a0.z, a0.w, a1.x, a1.y, a1.z, a1.w};
                #pragma unroll
                for (int r = 0; r < 8; ++r) {
                    ull ar = pack2(a[r], a[r]);
                    ffma2(acc[r][0], ar, b0);
                    ffma2(acc[r][1], ar, b1);
                    ffma2(acc[r][2], ar, b2);
                    ffma2(acc[r][3], ar, b3);
                }
            }
        }
        // epilogue: cols 0..127 -> silu -> sACT[n][k]; cols 128..255 -> sigmoid -> sGATE[n][k]
        #pragma unroll
        for (int r = 0; r < 8; ++r) {
            const int row = rg * 8 + r;
            float v[8];
            #pragma unroll
            for (int c = 0; c < 4; ++c) unpack2(acc[r][c], v[2 * c], v[2 * c + 1]);
            if (cg < 16) {
                float4 q0, q1;
                float t;
                t = v[0] * INV; q0.x = t * sigmoidf_(t);
                t = v[1] * INV; q0.y = t * sigmoidf_(t);
                t = v[2] * INV; q0.z = t * sigmoidf_(t);
                t = v[3] * INV; q0.w = t * sigmoidf_(t);
                t = v[4] * INV; q1.x = t * sigmoidf_(t);
                t = v[5] * INV; q1.y = t * sigmoidf_(t);
                t = v[6] * INV; q1.z = t * sigmoidf_(t);
                t = v[7] * INV; q1.w = t * sigmoidf_(t);
                *(float4*)&sACT[row * PA + cg * 8]     = q0;
                *(float4*)&sACT[row * PA + cg * 8 + 4] = q1;
            } else {
                float4 q0, q1;
                q0.x = sigmoidf_(v[0] * INV);
                q0.y = sigmoidf_(v[1] * INV);
                q0.z = sigmoidf_(v[2] * INV);
                q0.w = sigmoidf_(v[3] * INV);
                q1.x = sigmoidf_(v[4] * INV);
                q1.y = sigmoidf_(v[5] * INV);
                q1.z = sigmoidf_(v[6] * INV);
                q1.w = sigmoidf_(v[7] * INV);
                *(float4*)&sGATE[row * PG + (cg - 16) * 8]     = q0;
                *(float4*)&sGATE[row * PG + (cg - 16) * 8 + 4] = q1;
            }
        }
    }
    __syncthreads();   // sACT/sGATE visible; all G1-s readers of sX done

    // ======== L2-s: out_s = act @ w2_s * INV ========
    {
        const int n = tid >> 2, jg = tid & 3;
        float4 acc = {0.f, 0.f, 0.f, 0.f};
        #pragma unroll 8
        for (int k = 0; k < 128; ++k) {
            float a  = sACT[n * PA + k];
            float4 b = *(const float4*)&sW2S[k * 16 + jg * 4];
            acc.x = fmaf(a, b.x, acc.x);
            acc.y = fmaf(a, b.y, acc.y);
            acc.z = fmaf(a, b.z, acc.z);
            acc.w = fmaf(a, b.w, acc.w);
        }
        long row = tile0 + n;
        if (row < N) {
            float4 o = {acc.x * INV, acc.y * INV, acc.z * INV, acc.w * INV};
            *(float4*)&out[row * DOUT + jg * 4] = o;
        }
    }

    // ======== per-channel: G1-v, gate, L2-v ========
    for (int cc = 0; cc < 3; ++cc) {
        __syncthreads();   // all prior readers of sX done

        // stage v channel: sX[m][n]
        {
            int m = tid & 127, ng = tid >> 7;
            #pragma unroll 8
            for (int i = 0; i < 32; ++i) {
                int n = ng * 32 + i;
                long row = tile0 + n;
                float v = (row < N) ? x[row * DIN + MULD + m * 3 + cc] : 0.0f;
                sX[m * PX + n] = v;
            }
        }

        // G1-v: (128x128) @ w1_v(128x128); thread tile 4 rows x 8 cols
        const int rg = tid >> 4;      // 32 groups * 4 rows
        const int cg = tid & 15;      // 16 groups * 8 cols
        ull acc[4][4];
        #pragma unroll
        for (int r = 0; r < 4; ++r)
            #pragma unroll
            for (int c = 0; c < 4; ++c) acc[r][c] = 0ULL;

        const int lrow = tid >> 5;          // 0..15 (chunk = 16 k-rows x 128 cols)
        const int lcol = (tid * 4) & 127;
        float4 pre = *(const float4*)&w1v[lrow * 128 + lcol];

        for (int ch = 0; ch < 8; ++ch) {
            __syncthreads();
            *(float4*)&sW[lrow * 128 + lcol] = pre;
            if (ch + 1 < 8)
                pre = *(const float4*)&w1v[((ch + 1) * 16 + lrow) * 128 + lcol];
            __syncthreads();
            #pragma unroll
            for (int kk = 0; kk < 16; ++kk) {
                const int k = ch * 16 + kk;
                float4 a0 = *(const float4*)&sX[k * PX + rg * 4];
                const ull* bp = (const ull*)&sW[kk * 128 + cg * 8];
                ull b0 = bp[0], b1 = bp[1], b2 = bp[2], b3 = bp[3];
                float a[4] = {a0.x, a0.y, a0.z, a0.w};
                #pragma unroll
                for (int r = 0; r < 4; ++r) {
                    ull ar = pack2(a[r], a[r]);
                    ffma2(acc[r][0], ar, b0);
                    ffma2(acc[r][1], ar, b1);
                    ffma2(acc[r][2], ar, b2);
                    ffma2(acc[r][3], ar, b3);
                }
            }
        }

        // gate in registers
        float g8[4][8];
        #pragma unroll
        for (int r = 0; r < 4; ++r) {
            const int row = rg * 4 + r;
            float4 gg0 = *(const float4*)&sGATE[row * PG + cg * 8];
            float4 gg1 = *(const float4*)&sGATE[row * PG + cg * 8 + 4];
            float hv[8];
            #pragma unroll
            for (int c = 0; c < 4; ++c) unpack2(acc[r][c], hv[2 * c], hv[2 * c + 1]);
            g8[r][0] = hv[0] * INV * gg0.x;
            g8[r][1] = hv[1] * INV * gg0.y;
            g8[r][2] = hv[2] * INV * gg0.z;
            g8[r][3] = hv[3] * INV * gg0.w;
            g8[r][4] = hv[4] * INV * gg1.x;
            g8[r][5] = hv[5] * INV * gg1.y;
            g8[r][6] = hv[6] * INV * gg1.z;
            g8[r][7] = hv[7] * INV * gg1.w;
        }
        __syncthreads();   // done reading sX as v
        #pragma unroll
        for (int r = 0; r < 4; ++r) {
            const int row = rg * 4 + r;
            float4 q0 = {g8[r][0], g8[r][1], g8[r][2], g8[r][3]};
            float4 q1 = {g8[r][4], g8[r][5], g8[r][6], g8[r][7]};
            *(float4*)&sX[row * PX + cg * 8]     = q0;  // gated as [n][k]
            *(float4*)&sX[row * PX + cg * 8 + 4] = q1;
        }
        __syncthreads();   // gated visible

        // L2-v: out_v[:, :, cc] = gated @ w2_v * INV
        {
            const int n = tid >> 2, jg = tid & 3;
            float4 acc2 = {0.f, 0.f, 0.f, 0.f};
            #pragma unroll 8
            for (int k = 0; k < 128; ++k) {
                float a  = sX[n * PX + k];
                float4 b = *(const float4*)&sW2V[k * 16 + jg * 4];
                acc2.x = fmaf(a, b.x, acc2.x);
                acc2.y = fmaf(a, b.y, acc2.y);
                acc2.z = fmaf(a, b.z, acc2.z);
                acc2.w = fmaf(a, b.w, acc2.w);
            }
            long row = tile0 + n;
            if (row < N) {
                out[row * DOUT + 16 + (jg * 4 + 0) * 3 + cc] = acc2.x * INV;
                out[row * DOUT + 16 + (jg * 4 + 1) * 3 + cc] = acc2.y * INV;
                out[row * DOUT + 16 + (jg * 4 + 2) * 3 + cc] = acc2.z * INV;
                out[row * DOUT + 16 + (jg * 4 + 3) * 3 + cc] = acc2.w * INV;
            }
        }
    }
}

extern "C" void kernel_launch(void* const* d_in, const int* in_sizes, int n_in,
                              void* d_out, int out_size) {
    const float* x   = (const float*)d_in[0];
    const float* w1s = (const float*)d_in[1];
    const float* w1v = (const float*)d_in[2];
    const float* w2s = (const float*)d_in[3];
    const float* w2v = (const float*)d_in[4];
    float* out = (float*)d_out;

    const int N = in_sizes[0] / DIN;
    const int smem_bytes = SMEM_FLOATS * 4;

    cudaFuncSetAttribute(nlro_kernel, cudaFuncAttributeMaxDynamicSharedMemorySize,
                         smem_bytes);

    const int grid = (N + TILE_M - 1) / TILE_M;
    nlro_kernel<<<grid, THREADS, smem_bytes>>>(x, w1s, w1v, w2s, w2v, out, N);
}

// round 2
// speedup vs baseline: 1.2857x; 1.2857x over previous
#include <cuda_runtime.h>

// Fused NonLinearReadoutLayer, fp32 with packed f32x2 FFMA.
// Round 2: conflict-free B-fragment loads (two 4-col groups, 16B lane stride).

#define DIN     512
#define DOUT    64
#define MULD    128
#define TILE_M  128
#define THREADS 512

// smem pitches (floats)
#define PX 132   // sX  [k][n]  (also gated [n][k] later)
#define PA 132   // sACT [n][k]
#define PG 128   // sGATE [n][k]

// smem offsets (floats)
#define OFF_X    0
#define OFF_ACT  16896            // 128*132
#define OFF_GATE 33792            // + 128*132
#define OFF_W    50176            // + 128*128
#define OFF_W2S  52224            // + 2048 (weight chunk buf)
#define OFF_W2V  54272            // + 2048
#define SMEM_FLOATS 56320         // * 4 = 225280 bytes

typedef unsigned long long ull;

__device__ __forceinline__ ull pack2(float lo, float hi) {
    ull r; asm("mov.b64 %0, {%1, %2};" : "=l"(r) : "f"(lo), "f"(hi)); return r;
}
__device__ __forceinline__ void unpack2(ull v, float& lo, float& hi) {
    asm("mov.b64 {%0, %1}, %2;" : "=f"(lo), "=f"(hi) : "l"(v));
}
__device__ __forceinline__ void ffma2(ull& d, ull a, ull b) {
    asm("fma.rn.f32x2 %0, %1, %2, %0;" : "+l"(d) : "l"(a), "l"(b));
}
__device__ __forceinline__ float sigmoidf_(float x) {
    return __fdividef(1.0f, 1.0f + __expf(-x));
}

__global__ void __launch_bounds__(THREADS, 1)
nlro_kernel(const float* __restrict__ x,
            const float* __restrict__ w1s,
            const float* __restrict__ w1v,
            const float* __restrict__ w2s,
            const float* __restrict__ w2v,
            float* __restrict__ out, int N)
{
    extern __shared__ float sm[];
    float* sX    = sm + OFF_X;
    float* sACT  = sm + OFF_ACT;
    float* sGATE = sm + OFF_GATE;
    float* sW    = sm + OFF_W;
    float* sW2S  = sm + OFF_W2S;
    float* sW2V  = sm + OFF_W2V;

    const int  tid   = threadIdx.x;
    const long tile0 = (long)blockIdx.x * TILE_M;
    const float INV  = 0.08838834764831845f;   // 1/sqrt(128)

    // ---- stage w2_s, w2_v (2048 floats each) ----
    {
        float4 a = *(const float4*)&w2s[tid * 4];
        float4 b = *(const float4*)&w2v[tid * 4];
        *(float4*)&sW2S[tid * 4] = a;
        *(float4*)&sW2V[tid * 4] = b;
    }

    // ---- stage s-tile, transposed: sX[col][n] ----
    {
        int col = tid & 127, ng = tid >> 7;
        #pragma unroll 8
        for (int i = 0; i < 32; ++i) {
            int n = ng * 32 + i;
            long row = tile0 + n;
            float v = (row < N) ? x[row * DIN + col] : 0.0f;
            sX[col * PX + n] = v;
        }
    }

    // ======== G1-s: Hs = S(128x128) @ W1s(128x256) ========
    // thread tile 8 rows x (4 + 4) cols; col groups at cg*4 and 128+cg*4.
    {
        const int rg = tid >> 5;        // warp id: 16 row groups * 8 rows
        const int cg = tid & 31;        // lane: 32 col groups * 4 cols, two halves
        ull acc[8][4];
        #pragma unroll
        for (int r = 0; r < 8; ++r)
            #pragma unroll
            for (int c = 0; c < 4; ++c) acc[r][c] = 0ULL;

        const int lrow = tid >> 6;            // 0..7 (chunk = 8 k-rows x 256 cols)
        const int lcol = (tid * 4) & 255;
        float4 pre = *(const float4*)&w1s[lrow * 256 + lcol];

        for (int ch = 0; ch < 16; ++ch) {
            __syncthreads();                              // prev chunk fully consumed
            *(float4*)&sW[lrow * 256 + lcol] = pre;
            if (ch + 1 < 16)
                pre = *(const float4*)&w1s[((ch + 1) * 8 + lrow) * 256 + lcol];
            __syncthreads();                              // chunk (and staging) visible
            #pragma unroll
            for (int kk = 0; kk < 8; ++kk) {
                const int k = ch * 8 + kk;
                float4 a0 = *(const float4*)&sX[k * PX + rg * 8];        // broadcast
                float4 a1 = *(const float4*)&sX[k * PX + rg * 8 + 4];
                longlong2 bA = *(const longlong2*)&sW[kk * 256 + cg * 4];        // 16B lane stride
                longlong2 bB = *(const longlong2*)&sW[kk * 256 + 128 + cg * 4];
                ull b0 = (ull)bA.x, b1 = (ull)bA.y, b2 = (ull)bB.x, b3 = (ull)bB.y;
                float a[8] = {a0.x, a0.y, a0.z, a0.w, a1.x, a1.y, a1.z, a1.w};
                #pragma unroll
                for (int r = 0; r < 8; ++r) {
                    ull ar = pack2(a[r], a[r]);
                    ffma2(acc[r][0], ar, b0);
                    ffma2(acc[r][1], ar, b1);
                    ffma2(acc[r][2], ar, b2);
                    ffma2(acc[r][3], ar, b3);
                }
            }
        }
        // epilogue: group A (cols cg*4, <128) -> silu -> sACT[n][k]
        //           group B (cols 128+cg*4)   -> sigmoid -> sGATE[n][k]
        #pragma unroll
        for (int r = 0; r < 8; ++r) {
            const int row = rg * 8 + r;
            float v[8];
            unpack2(acc[r][0], v[0], v[1]);
            unpack2(acc[r][1], v[2], v[3]);
            unpack2(acc[r][2], v[4], v[5]);
            unpack2(acc[r][3], v[6], v[7]);
            float4 qa, qg;
            float t;
            t = v[0] * INV; qa.x = t * sigmoidf_(t);
            t = v[1] * INV; qa.y = t * sigmoidf_(t);
            t = v[2] * INV; qa.z = t * sigmoidf_(t);
            t = v[3] * INV; qa.w = t * sigmoidf_(t);
            qg.x = sigmoidf_(v[4] * INV);
            qg.y = sigmoidf_(v[5] * INV);
            qg.z = sigmoidf_(v[6] * INV);
            qg.w = sigmoidf_(v[7] * INV);
            *(float4*)&sACT [row * PA + cg * 4] = qa;
            *(float4*)&sGATE[row * PG + cg * 4] = qg;
        }
    }
    __syncthreads();   // sACT/sGATE visible; all G1-s readers of sX done

    // ======== L2-s: out_s = act @ w2_s * INV ========
    {
        const int n = tid >> 2, jg = tid & 3;
        float4 acc = {0.f, 0.f, 0.f, 0.f};
        #pragma unroll 8
        for (int k = 0; k < 128; ++k) {
            float a  = sACT[n * PA + k];
            float4 b = *(const float4*)&sW2S[k * 16 + jg * 4];
            acc.x = fmaf(a, b.x, acc.x);
            acc.y = fmaf(a, b.y, acc.y);
            acc.z = fmaf(a, b.z, acc.z);
            acc.w = fmaf(a, b.w, acc.w);
        }
        long row = tile0 + n;
        if (row < N) {
            float4 o = {acc.x * INV, acc.y * INV, acc.z * INV, acc.w * INV};
            *(float4*)&out[row * DOUT + jg * 4] = o;
        }
    }

    // ======== per-channel: G1-v, gate, L2-v ========
    for (int cc = 0; cc < 3; ++cc) {
        __syncthreads();   // all prior readers of sX done

        // stage v channel: sX[m][n]
        {
            int m = tid & 127, ng = tid >> 7;
            #pragma unroll 8
            for (int i = 0; i < 32; ++i) {
                int n = ng * 32 + i;
                long row = tile0 + n;
                float v = (row < N) ? x[row * DIN + MULD + m * 3 + cc] : 0.0f;
                sX[m * PX + n] = v;
            }
        }

        // G1-v: (128x128) @ w1_v(128x128); thread tile 4 rows x (4+4) cols
        const int rg = tid >> 4;      // 32 groups * 4 rows
        const int cg = tid & 15;      // 16 col groups * 4 cols, two halves (+64)
        ull acc[4][4];
        #pragma unroll
        for (int r = 0; r < 4; ++r)
            #pragma unroll
            for (int c = 0; c < 4; ++c) acc[r][c] = 0ULL;

        const int lrow = tid >> 5;          // 0..15 (chunk = 16 k-rows x 128 cols)
        const int lcol = (tid * 4) & 127;
        float4 pre = *(const float4*)&w1v[lrow * 128 + lcol];

        for (int ch = 0; ch < 8; ++ch) {
            __syncthreads();
            *(float4*)&sW[lrow * 128 + lcol] = pre;
            if (ch + 1 < 8)
                pre = *(const float4*)&w1v[((ch + 1) * 16 + lrow) * 128 + lcol];
            __syncthreads();
            #pragma unroll
            for (int kk = 0; kk < 16; ++kk) {
                const int k = ch * 16 + kk;
                float4 a0 = *(const float4*)&sX[k * PX + rg * 4];        // broadcast
                longlong2 bA = *(const longlong2*)&sW[kk * 128 + cg * 4];
                longlong2 bB = *(const longlong2*)&sW[kk * 128 + 64 + cg * 4];
                ull b0 = (ull)bA.x, b1 = (ull)bA.y, b2 = (ull)bB.x, b3 = (ull)bB.y;
                float a[4] = {a0.x, a0.y, a0.z, a0.w};
                #pragma unroll
                for (int r = 0; r < 4; ++r) {
                    ull ar = pack2(a[r], a[r]);
                    ffma2(acc[r][0], ar, b0);
                    ffma2(acc[r][1], ar, b1);
                    ffma2(acc[r][2], ar, b2);
                    ffma2(acc[r][3], ar, b3);
                }
            }
        }

        // gate in registers; cols: cg*4 (group A), 64+cg*4 (group B)
        float g8[4][8];
        #pragma unroll
        for (int r = 0; r < 4; ++r) {
            const int row = rg * 4 + r;
            float4 gg0 = *(const float4*)&sGATE[row * PG + cg * 4];
            float4 gg1 = *(const float4*)&sGATE[row * PG + 64 + cg * 4];
            float hv[8];
            unpack2(acc[r][0], hv[0], hv[1]);
            unpack2(acc[r][1], hv[2], hv[3]);
            unpack2(acc[r][2], hv[4], hv[5]);
            unpack2(acc[r][3], hv[6], hv[7]);
            g8[r][0] = hv[0] * INV * gg0.x;
            g8[r][1] = hv[1] * INV * gg0.y;
            g8[r][2] = hv[2] * INV * gg0.z;
            g8[r][3] = hv[3] * INV * gg0.w;
            g8[r][4] = hv[4] * INV * gg1.x;
            g8[r][5] = hv[5] * INV * gg1.y;
            g8[r][6] = hv[6] * INV * gg1.z;
            g8[r][7] = hv[7] * INV * gg1.w;
        }
        __syncthreads();   // done reading sX as v
        #pragma unroll
        for (int r = 0; r < 4; ++r) {
            const int row = rg * 4 + r;
            float4 q0 = {g8[r][0], g8[r][1], g8[r][2], g8[r][3]};
            float4 q1 = {g8[r][4], g8[r][5], g8[r][6], g8[r][7]};
            *(float4*)&sX[row * PX + cg * 4]      = q0;  // gated as [n][k]
            *(float4*)&sX[row * PX + 64 + cg * 4] = q1;
        }
        __syncthreads();   // gated visible

        // L2-v: out_v[:, :, cc] = gated @ w2_v * INV
        {
            const int n = tid >> 2, jg = tid & 3;
            float4 acc2 = {0.f, 0.f, 0.f, 0.f};
            #pragma unroll 8
            for (int k = 0; k < 128; ++k) {
                float a  = sX[n * PX + k];
                float4 b = *(const float4*)&sW2V[k * 16 + jg * 4];
                acc2.x = fmaf(a, b.x, acc2.x);
                acc2.y = fmaf(a, b.y, acc2.y);
                acc2.z = fmaf(a, b.z, acc2.z);
                acc2.w = fmaf(a, b.w, acc2.w);
            }
            long row = tile0 + n;
            if (row < N) {
                out[row * DOUT + 16 + (jg * 4 + 0) * 3 + cc] = acc2.x * INV;
                out[row * DOUT + 16 + (jg * 4 + 1) * 3 + cc] = acc2.y * INV;
                out[row * DOUT + 16 + (jg * 4 + 2) * 3 + cc] = acc2.z * INV;
                out[row * DOUT + 16 + (jg * 4 + 3) * 3 + cc] = acc2.w * INV;
            }
        }
    }
}

extern "C" void kernel_launch(void* const* d_in, const int* in_sizes, int n_in,
                              void* d_out, int out_size) {
    const float* x   = (const float*)d_in[0];
    const float* w1s = (const float*)d_in[1];
    const float* w1v = (const float*)d_in[2];
    const float* w2s = (const float*)d_in[3];
    const float* w2v = (const float*)d_in[4];
    float* out = (float*)d_out;

    const int N = in_sizes[0] / DIN;
    const int smem_bytes = SMEM_FLOATS * 4;

    cudaFuncSetAttribute(nlro_kernel, cudaFuncAttributeMaxDynamicSharedMemorySize,
                         smem_bytes);

    const int grid = (N + TILE_M - 1) / TILE_M;
    nlro_kernel<<<grid, THREADS, smem_bytes>>>(x, w1s, w1v, w2s, w2v, out, N);
}

// round 4
// speedup vs baseline: 1.9802x; 1.5402x over previous
#include <cuda_runtime.h>
#include <cuda_fp16.h>
#include <cstdint>

// Fused NonLinearReadoutLayer via mma.sync.m16n8k16 (fp16 in, fp32 accum).
// A-operands split hi/lo fp16 (2 passes) except x_v (single); B single fp16.

#define DIN     512
#define TILE_M  128
#define THREADS 512

// pitches in halves
#define PA 136
#define PB 136
#define PW 24
#define PG 132

// smem byte offsets
#define OFF_A1H  0u         // x_s hi -> act hi -> v_ch0 -> gated hi(ch0)
#define OFF_A1L  34816u     // x_s lo -> act lo -> v_ch1 -> gated hi(ch1)
#define OFF_B    69632u     // streamed B: w1s h1 -> w1s h0 -> w1v
#define OFF_GATE 104448u    // gates fp16 [128][PG]
#define OFF_W2S  138240u
#define OFF_W2V  144384u
#define OFF_V2   150528u    // v_ch2 -> gated hi(ch2)
#define OFF_GL   185344u    // gated lo (reused per channel)
#define SMEM_BYTES 220160u

__device__ __align__(16) __half g_w1s[2][128 * PB];
__device__ __align__(16) __half g_w1v[128 * PB];
__device__ __align__(16) __half g_w2s[128 * PW];
__device__ __align__(16) __half g_w2v[128 * PW];

// ---------------------------------------------------------------- helpers
__device__ __forceinline__ uint32_t smem_u32(const void* p) {
    uint32_t a;
    asm("{ .reg .u64 t; cvta.to.shared.u64 t, %1; cvt.u32.u64 %0, t; }"
        : "=r"(a) : "l"(p));
    return a;
}
__device__ __forceinline__ uint32_t h2u(__half2 h) {
    return *reinterpret_cast<uint32_t*>(&h);
}
__device__ __forceinline__ float sigf(float x) {
    return __fdividef(1.0f, 1.0f + __expf(-x));
}
__device__ __forceinline__ void ldsm4(uint32_t* r, uint32_t addr) {
    asm volatile("ldmatrix.sync.aligned.m8n8.x4.shared.b16 {%0,%1,%2,%3}, [%4];"
                 : "=r"(r[0]), "=r"(r[1]), "=r"(r[2]), "=r"(r[3]) : "r"(addr));
}
__device__ __forceinline__ void ldsm4t(uint32_t* r, uint32_t addr) {
    asm volatile("ldmatrix.sync.aligned.m8n8.x4.trans.shared.b16 {%0,%1,%2,%3}, [%4];"
                 : "=r"(r[0]), "=r"(r[1]), "=r"(r[2]), "=r"(r[3]) : "r"(addr));
}
__device__ __forceinline__ void mma16816(float* c, const uint32_t* a, const uint32_t* b) {
    asm volatile(
        "mma.sync.aligned.m16n8k16.row.col.f32.f16.f16.f32 "
        "{%0,%1,%2,%3}, {%4,%5,%6,%7}, {%8,%9}, {%0,%1,%2,%3};"
        : "+f"(c[0]), "+f"(c[1]), "+f"(c[2]), "+f"(c[3])
        : "r"(a[0]), "r"(a[1]), "r"(a[2]), "r"(a[3]), "r"(b[0]), "r"(b[1]));
}
// K=128 GEMM slab: 8 k16 steps, NG n16-groups per warp.
template <int NG>
__device__ __forceinline__ void gemm8(float (*acc)[4], uint32_t aAddr,
                                      uint32_t bAddr, uint32_t pbB) {
    #pragma unroll
    for (int k = 0; k < 8; ++k) {
        uint32_t a[4];
        ldsm4(a, aAddr + k * 32);
        #pragma unroll
        for (int g = 0; g < NG; ++g) {
            uint32_t b[4];
            ldsm4t(b, bAddr + k * 16 * pbB + g * 32);
            mma16816(acc[2 * g],     a, b);
            mma16816(acc[2 * g + 1], a, b + 2);
        }
    }
}
__device__ __forceinline__ void split2(float v0, float v1, uint32_t& hi, uint32_t& lo) {
    __half2 h = __floats2half2_rn(v0, v1);
    float2 hf = __half22float2(h);
    __half2 l = __floats2half2_rn(v0 - hf.x, v1 - hf.y);
    hi = h2u(h);
    lo = h2u(l);
}

// ---------------------------------------------------------------- prep
__global__ void prep(const float* __restrict__ w1s, const float* __restrict__ w1v,
                     const float* __restrict__ w2s, const float* __restrict__ w2v) {
    int idx = blockIdx.x * blockDim.x + threadIdx.x;
    int stride = gridDim.x * blockDim.x;
    for (int i = idx; i < 2 * 128 * 128; i += stride) {
        int h = i >> 14, k = (i >> 7) & 127, n = i & 127;
        g_w1s[h][k * PB + n] = __float2half_rn(w1s[k * 256 + h * 128 + n]);
    }
    for (int i = idx; i < 128 * 128; i += stride)
        g_w1v[(i >> 7) * PB + (i & 127)] = __float2half_rn(w1v[i]);
    for (int i = idx; i < 128 * 16; i += stride) {
        int k = i >> 4, n = i & 15;
        g_w2s[k * PW + n] = __float2half_rn(w2s[i]);
        g_w2v[k * PW + n] = __float2half_rn(w2v[i]);
    }
}

// ---------------------------------------------------------------- main
__global__ void __launch_bounds__(THREADS, 1)
nlro(const float* __restrict__ x, float* __restrict__ out, int N) {
    extern __shared__ char sm[];
    const uint32_t smb = smem_u32(sm);
    const int tid = threadIdx.x, lane = tid & 31, wid = tid >> 5;
    const int wm = wid & 7, wn = wid >> 3;
    const long tile0 = (long)blockIdx.x * TILE_M;
    const float INV = 0.08838834764831845f;

    const int row0 = wm * 16 + (lane >> 2);      // fragment row (G1 warps)
    const int cpair = 2 * (lane & 3);            // fragment col pair base
    // lane components for ldmatrix addressing
    const int l16 = lane & 15, lhi = lane >> 4;

    // ======== phase 0: stage x_s hi/lo, B<-w1s half1, W2 images ========
    {
        int n = tid >> 2, kg = tid & 3;
        long row = tile0 + n;
        bool ok = row < N;
        const float4* xp = (const float4*)(x + row * DIN + kg * 32);
        char* dh = sm + OFF_A1H + (n * PA + kg * 32) * 2;
        char* dl = sm + OFF_A1L + (n * PA + kg * 32) * 2;
        #pragma unroll
        for (int t = 0; t < 8; ++t) {
            float4 v = ok ? xp[t] : make_float4(0.f, 0.f, 0.f, 0.f);
            uint32_t h0, l0, h1, l1;
            split2(v.x, v.y, h0, l0);
            split2(v.z, v.w, h1, l1);
            *(uint2*)(dh + t * 8) = make_uint2(h0, h1);
            *(uint2*)(dl + t * 8) = make_uint2(l0, l1);
        }
        const float4* s1 = (const float4*)&g_w1s[1][0];
        float4* db = (float4*)(sm + OFF_B);
        for (int i = tid; i < 2176; i += THREADS) db[i] = s1[i];
        const float4* s2s = (const float4*)g_w2s;
        const float4* s2v = (const float4*)g_w2v;
        float4* d2s = (float4*)(sm + OFF_W2S);
        float4* d2v = (float4*)(sm + OFF_W2V);
        for (int i = tid; i < 384; i += THREADS) { d2s[i] = s2s[i]; d2v[i] = s2v[i]; }
    }
    __syncthreads();

    const uint32_t aOffLane = ((wm * 16 + l16) * PA + lhi * 8) * 2;
    const uint32_t bOffLane = (l16 * PB + wn * 64 + lhi * 8) * 2;

    // ======== G1-s half1 (gates) ========
    {
        float acc[8][4] = {};
        gemm8<4>(acc, smb + OFF_A1H + aOffLane, smb + OFF_B + bOffLane, PB * 2);
        gemm8<4>(acc, smb + OFF_A1L + aOffLane, smb + OFF_B + bOffLane, PB * 2);
        __syncthreads();   // B consumed
        #pragma unroll
        for (int t = 0; t < 8; ++t) {
            int col = wn * 64 + 8 * t + cpair;
            __half2 g0 = __floats2half2_rn(sigf(INV * acc[t][0]), sigf(INV * acc[t][1]));
            __half2 g1 = __floats2half2_rn(sigf(INV * acc[t][2]), sigf(INV * acc[t][3]));
            *(uint32_t*)(sm + OFF_GATE + (row0 * PG + col) * 2) = h2u(g0);
            *(uint32_t*)(sm + OFF_GATE + ((row0 + 8) * PG + col) * 2) = h2u(g1);
        }
        const float4* s0 = (const float4*)&g_w1s[0][0];
        float4* db = (float4*)(sm + OFF_B);
        for (int i = tid; i < 2176; i += THREADS) db[i] = s0[i];
    }
    __syncthreads();

    // ======== G1-s half0 (act) ========
    {
        float acc[8][4] = {};
        gemm8<4>(acc, smb + OFF_A1H + aOffLane, smb + OFF_B + bOffLane, PB * 2);
        gemm8<4>(acc, smb + OFF_A1L + aOffLane, smb + OFF_B + bOffLane, PB * 2);
        __syncthreads();   // x_s dead, B(h0) consumed
        #pragma unroll
        for (int t = 0; t < 8; ++t) {
            int col = wn * 64 + 8 * t + cpair;
            float a0 = INV * acc[t][0], a1 = INV * acc[t][1];
            float a2 = INV * acc[t][2], a3 = INV * acc[t][3];
            a0 *= sigf(a0); a1 *= sigf(a1); a2 *= sigf(a2); a3 *= sigf(a3);
            uint32_t h0, l0, h1, l1;
            split2(a0, a1, h0, l0);
            split2(a2, a3, h1, l1);
            *(uint32_t*)(sm + OFF_A1H + (row0 * PA + col) * 2) = h0;
            *(uint32_t*)(sm + OFF_A1L + (row0 * PA + col) * 2) = l0;
            *(uint32_t*)(sm + OFF_A1H + ((row0 + 8) * PA + col) * 2) = h1;
            *(uint32_t*)(sm + OFF_A1L + ((row0 + 8) * PA + col) * 2) = l1;
        }
    }
    __syncthreads();   // act visible

    // ======== L2-s (warps 0-7) || w1v copy (warps 8-15) ========
    if (wid < 8) {
        float acc[2][4] = {};
        uint32_t aOff = ((wid * 16 + l16) * PA + lhi * 8) * 2;
        uint32_t bOff = (l16 * PW + lhi * 8) * 2;
        gemm8<1>(acc, smb + OFF_A1H + aOff, smb + OFF_W2S + bOff, PW * 2);
        gemm8<1>(acc, smb + OFF_A1L + aOff, smb + OFF_W2S + bOff, PW * 2);
        int r0 = wid * 16 + (lane >> 2);
        long gr0 = tile0 + r0, gr1 = gr0 + 8;
        if (gr0 < N) {
            *(float2*)&out[gr0 * 64 + cpair]     = make_float2(INV * acc[0][0], INV * acc[0][1]);
            *(float2*)&out[gr0 * 64 + cpair + 8] = make_float2(INV * acc[1][0], INV * acc[1][1]);
        }
        if (gr1 < N) {
            *(float2*)&out[gr1 * 64 + cpair]     = make_float2(INV * acc[0][2], INV * acc[0][3]);
            *(float2*)&out[gr1 * 64 + cpair + 8] = make_float2(INV * acc[1][2], INV * acc[1][3]);
        }
    } else {
        const float4* sv = (const float4*)g_w1v;
        float4* db = (float4*)(sm + OFF_B);
        for (int i = tid - 256; i < 2176; i += 256) db[i] = sv[i];
    }
    __syncthreads();   // act dead, B=w1v ready

    // ======== stage all 3 v channels in one vectorized pass ========
    {
        int n = tid >> 2, mg = tid & 3;
        long row = tile0 + n;
        bool ok = row < N;
        const float4* vp = (const float4*)(x + row * DIN + 128 + mg * 96);
        uint32_t rb = (n * PA + mg * 32) * 2;
        char* b0 = sm + OFF_A1H + rb;
        char* b1 = sm + OFF_A1L + rb;
        char* b2 = sm + OFF_V2 + rb;
        #pragma unroll
        for (int blk = 0; blk < 4; ++blk) {
            float f[24];
            #pragma unroll
            for (int j = 0; j < 6; ++j) {
                float4 t = ok ? vp[blk * 6 + j] : make_float4(0.f, 0.f, 0.f, 0.f);
                f[4 * j] = t.x; f[4 * j + 1] = t.y; f[4 * j + 2] = t.z; f[4 * j + 3] = t.w;
            }
            uint4 u0, u1, u2;
            u0.x = h2u(__floats2half2_rn(f[0],  f[3]));
            u0.y = h2u(__floats2half2_rn(f[6],  f[9]));
            u0.z = h2u(__floats2half2_rn(f[12], f[15]));
            u0.w = h2u(__floats2half2_rn(f[18], f[21]));
            u1.x = h2u(__floats2half2_rn(f[1],  f[4]));
            u1.y = h2u(__floats2half2_rn(f[7],  f[10]));
            u1.z = h2u(__floats2half2_rn(f[13], f[16]));
            u1.w = h2u(__floats2half2_rn(f[19], f[22]));
            u2.x = h2u(__floats2half2_rn(f[2],  f[5]));
            u2.y = h2u(__floats2half2_rn(f[8],  f[11]));
            u2.z = h2u(__floats2half2_rn(f[14], f[17]));
            u2.w = h2u(__floats2half2_rn(f[20], f[23]));
            *(uint4*)(b0 + blk * 16) = u0;
            *(uint4*)(b1 + blk * 16) = u1;
            *(uint4*)(b2 + blk * 16) = u2;
        }
    }
    __syncthreads();

    // ======== per-channel: G1-v -> gate -> L2-v ========
    #pragma unroll 1
    for (int c = 0; c < 3; ++c) {
        uint32_t chOff = (c == 0) ? OFF_A1H : (c == 1) ? OFF_A1L : OFF_V2;

        float acc[8][4] = {};
        gemm8<4>(acc, smb + chOff + aOffLane, smb + OFF_B + bOffLane, PB * 2);
        __syncthreads();   // channel buffer consumed

        #pragma unroll
        for (int t = 0; t < 8; ++t) {
            int col = wn * 64 + 8 * t + cpair;
            float2 g0 = __half22float2(*(__half2*)(sm + OFF_GATE + (row0 * PG + col) * 2));
            float2 g1 = __half22float2(*(__half2*)(sm + OFF_GATE + ((row0 + 8) * PG + col) * 2));
            float v0 = INV * acc[t][0] * g0.x, v1 = INV * acc[t][1] * g0.y;
            float v2 = INV * acc[t][2] * g1.x, v3 = INV * acc[t][3] * g1.y;
            uint32_t h0, l0, h1, l1;
            split2(v0, v1, h0, l0);
            split2(v2, v3, h1, l1);
            *(uint32_t*)(sm + chOff + (row0 * PA + col) * 2) = h0;
            *(uint32_t*)(sm + OFF_GL + (row0 * PA + col) * 2) = l0;
            *(uint32_t*)(sm + chOff + ((row0 + 8) * PA + col) * 2) = h1;
            *(uint32_t*)(sm + OFF_GL + ((row0 + 8) * PA + col) * 2) = l1;
        }
        __syncthreads();   // gated visible

        if (wid < 8) {
            float acc2[2][4] = {};
            uint32_t aOff = ((wid * 16 + l16) * PA + lhi * 8) * 2;
            uint32_t bOff = (l16 * PW + lhi * 8) * 2;
            gemm8<1>(acc2, smb + chOff + aOff, smb + OFF_W2V + bOff, PW * 2);
            gemm8<1>(acc2, smb + OFF_GL + aOff, smb + OFF_W2V + bOff, PW * 2);
            int r0 = wid * 16 + (lane >> 2);
            long gr0 = tile0 + r0, gr1 = gr0 + 8;
            if (gr0 < N) {
                float* op = out + gr0 * 64 + 16 + c;
                op[(cpair) * 3]     = INV * acc2[0][0];
                op[(cpair + 1) * 3] = INV * acc2[0][1];
                op[(cpair + 8) * 3] = INV * acc2[1][0];
                op[(cpair + 9) * 3] = INV * acc2[1][1];
            }
            if (gr1 < N) {
                float* op = out + gr1 * 64 + 16 + c;
                op[(cpair) * 3]     = INV * acc2[0][2];
                op[(cpair + 1) * 3] = INV * acc2[0][3];
                op[(cpair + 8) * 3] = INV * acc2[1][2];
                op[(cpair + 9) * 3] = INV * acc2[1][3];
            }
        }
        __syncthreads();   // OFF_GL / chan buffers reusable
    }
}

// ---------------------------------------------------------------- launch
extern "C" void kernel_launch(void* const* d_in, const int* in_sizes, int n_in,
                              void* d_out, int out_size) {
    const float* x   = (const float*)d_in[0];
    const float* w1s = (const float*)d_in[1];
    const float* w1v = (const float*)d_in[2];
    const float* w2s = (const float*)d_in[3];
    const float* w2v = (const float*)d_in[4];
    float* out = (float*)d_out;

    const int N = in_sizes[0] / DIN;

    prep<<<64, 256>>>(w1s, w1v, w2s, w2v);

    cudaFuncSetAttribute(nlro, cudaFuncAttributeMaxDynamicSharedMemorySize,
                         SMEM_BYTES);
    const int grid = (N + TILE_M - 1) / TILE_M;
    nlro<<<grid, THREADS, SMEM_BYTES>>>(x, out, N);
}

// round 5
// speedup vs baseline: 2.2278x; 1.1250x over previous
#include <cuda_runtime.h>
#include <cuda_fp16.h>
#include <cstdint>

// Fused NonLinearReadoutLayer via mma.sync.m16n8k16 (fp16 in, fp32 accum).
// Single-fp16 operands everywhere; act/gated stay in registers (C-frag == A-frag).
// 256 threads/CTA, 2 CTAs/SM; warp-local A/GATE => channel loop is barrier-free.

#define DIN     512
#define TILE_M  128
#define THREADS 256

// pitches in halves
#define PA 136
#define PB 136
#define PG 128
#define PW 24

// smem byte offsets
#define OFF_A    0u          // x_s -> v_c (staging)          34816
#define OFF_B    34816u      // w1s h1 -> w1s h0 -> w1v       34816
#define OFF_GATE 69632u      // gates fp16 [128][128]         32768
#define OFF_W2S  102400u     //                                6144
#define OFF_W2V  108544u     //                                6144
#define SMEM_BYTES 114688u

__device__ __align__(16) __half g_w1s[2][128 * PB];
__device__ __align__(16) __half g_w1v[128 * PB];
__device__ __align__(16) __half g_w2s[128 * PW];
__device__ __align__(16) __half g_w2v[128 * PW];

// ---------------------------------------------------------------- helpers
__device__ __forceinline__ uint32_t smem_u32(const void* p) {
    uint32_t a;
    asm("{ .reg .u64 t; cvta.to.shared.u64 t, %1; cvt.u32.u64 %0, t; }"
        : "=r"(a) : "l"(p));
    return a;
}
__device__ __forceinline__ uint32_t h2u(__half2 h) {
    return *reinterpret_cast<uint32_t*>(&h);
}
__device__ __forceinline__ float sigf(float x) {
    return __fdividef(1.0f, 1.0f + __expf(-x));
}
__device__ __forceinline__ void ldsm4(uint32_t* r, uint32_t addr) {
    asm volatile("ldmatrix.sync.aligned.m8n8.x4.shared.b16 {%0,%1,%2,%3}, [%4];"
                 : "=r"(r[0]), "=r"(r[1]), "=r"(r[2]), "=r"(r[3]) : "r"(addr));
}
__device__ __forceinline__ void ldsm4t(uint32_t* r, uint32_t addr) {
    asm volatile("ldmatrix.sync.aligned.m8n8.x4.trans.shared.b16 {%0,%1,%2,%3}, [%4];"
                 : "=r"(r[0]), "=r"(r[1]), "=r"(r[2]), "=r"(r[3]) : "r"(addr));
}
__device__ __forceinline__ void mma16816(float* c, const uint32_t* a, const uint32_t* b) {
    asm volatile(
        "mma.sync.aligned.m16n8k16.row.col.f32.f16.f16.f32 "
        "{%0,%1,%2,%3}, {%4,%5,%6,%7}, {%8,%9}, {%0,%1,%2,%3};"
        : "+f"(c[0]), "+f"(c[1]), "+f"(c[2]), "+f"(c[3])
        : "r"(a[0]), "r"(a[1]), "r"(a[2]), "r"(a[3]), "r"(b[0]), "r"(b[1]));
}
// K=128 GEMM slab from smem A and smem B: 8 k16 steps, NG n16-groups.
template <int NG>
__device__ __forceinline__ void gemm8(float (*acc)[4], uint32_t aAddr,
                                      uint32_t bAddr, uint32_t pbB) {
    #pragma unroll
    for (int k = 0; k < 8; ++k) {
        uint32_t a[4];
        ldsm4(a, aAddr + k * 32);
        #pragma unroll
        for (int g = 0; g < NG; ++g) {
            uint32_t b[4];
            ldsm4t(b, bAddr + k * 16 * pbB + g * 32);
            mma16816(acc[2 * g],     a, b);
            mma16816(acc[2 * g + 1], a, b + 2);
        }
    }
}
// K=128 GEMM with A from registers (afrag[32] = 8 kb x 4 regs), B from smem, NG=1.
__device__ __forceinline__ void gemm8_regA(float (*acc)[4], const uint32_t* afrag,
                                           uint32_t bAddr, uint32_t pbB) {
    #pragma unroll
    for (int kb = 0; kb < 8; ++kb) {
        uint32_t b[4];
        ldsm4t(b, bAddr + kb * 16 * pbB);
        mma16816(acc[0], afrag + 4 * kb, b);
        mma16816(acc[1], afrag + 4 * kb, b + 2);
    }
}

// ---------------------------------------------------------------- prep
__global__ void prep(const float* __restrict__ w1s, const float* __restrict__ w1v,
                     const float* __restrict__ w2s, const float* __restrict__ w2v) {
    int idx = blockIdx.x * blockDim.x + threadIdx.x;
    int stride = gridDim.x * blockDim.x;
    for (int i = idx; i < 2 * 128 * 128; i += stride) {
        int h = i >> 14, k = (i >> 7) & 127, n = i & 127;
        g_w1s[h][k * PB + n] = __float2half_rn(w1s[k * 256 + h * 128 + n]);
    }
    for (int i = idx; i < 128 * 128; i += stride)
        g_w1v[(i >> 7) * PB + (i & 127)] = __float2half_rn(w1v[i]);
    for (int i = idx; i < 128 * 16; i += stride) {
        int k = i >> 4, n = i & 15;
        g_w2s[k * PW + n] = __float2half_rn(w2s[i]);
        g_w2v[k * PW + n] = __float2half_rn(w2v[i]);
    }
}

// ---------------------------------------------------------------- main
__global__ void __launch_bounds__(THREADS, 2)
nlro(const float* __restrict__ x, float* __restrict__ out, int N) {
    extern __shared__ char sm[];
    const uint32_t smb = smem_u32(sm);
    const int tid = threadIdx.x, lane = tid & 31, wid = tid >> 5;
    const long tile0 = (long)blockIdx.x * TILE_M;
    const float INV = 0.08838834764831845f;

    const int row0 = wid * 16 + (lane >> 2);
    const int cpair = 2 * (lane & 3);
    const int l16 = lane & 15, lhi = lane >> 4;

    const uint32_t aOff  = smb + OFF_A + ((wid * 16 + l16) * PA + lhi * 8) * 2;
    const uint32_t bOff  = smb + OFF_B + (l16 * PB + lhi * 8) * 2;
    const uint32_t bOffS = smb + OFF_W2S + (l16 * PW + lhi * 8) * 2;
    const uint32_t bOffV = smb + OFF_W2V + (l16 * PW + lhi * 8) * 2;

    // ======== phase 0: stage x_s fp16 -> A; B <- w1s[1]; W2 images ========
    {
        int n = tid >> 1, kg = tid & 1;
        long row = tile0 + n;
        bool ok = row < N;
        const float4* xp = (const float4*)(x + row * DIN + kg * 64);
        char* dst = sm + OFF_A + (n * PA + kg * 64) * 2;
        #pragma unroll
        for (int t = 0; t < 8; ++t) {
            float4 v0 = ok ? xp[2 * t]     : make_float4(0.f, 0.f, 0.f, 0.f);
            float4 v1 = ok ? xp[2 * t + 1] : make_float4(0.f, 0.f, 0.f, 0.f);
            uint4 u;
            u.x = h2u(__floats2half2_rn(v0.x, v0.y));
            u.y = h2u(__floats2half2_rn(v0.z, v0.w));
            u.z = h2u(__floats2half2_rn(v1.x, v1.y));
            u.w = h2u(__floats2half2_rn(v1.z, v1.w));
            *(uint4*)(dst + t * 16) = u;
        }
        const float4* s1 = (const float4*)&g_w1s[1][0];
        float4* db = (float4*)(sm + OFF_B);
        for (int i = tid; i < 2176; i += THREADS) db[i] = s1[i];
        const float4* s2s = (const float4*)g_w2s;
        const float4* s2v = (const float4*)g_w2v;
        float4* d2s = (float4*)(sm + OFF_W2S);
        float4* d2v = (float4*)(sm + OFF_W2V);
        for (int i = tid; i < 384; i += THREADS) { d2s[i] = s2s[i]; d2v[i] = s2v[i]; }
    }
    __syncthreads();

    // ======== gates: h_s[:,128:] -> sigmoid -> GATE (two 64-col halves) ====
    #pragma unroll
    for (int h = 0; h < 2; ++h) {
        float acc[8][4] = {};
        gemm8<4>(acc, aOff, bOff + h * 128, PB * 2);
        #pragma unroll
        for (int t = 0; t < 8; ++t) {
            int col = h * 64 + 8 * t + cpair;
            *(uint32_t*)(sm + OFF_GATE + (row0 * PG + col) * 2) =
                h2u(__floats2half2_rn(sigf(INV * acc[t][0]), sigf(INV * acc[t][1])));
            *(uint32_t*)(sm + OFF_GATE + ((row0 + 8) * PG + col) * 2) =
                h2u(__floats2half2_rn(sigf(INV * acc[t][2]), sigf(INV * acc[t][3])));
        }
    }
    __syncthreads();               // B (w1s h1) consumed by all warps

    {   // B <- w1s[0]
        const float4* s0 = (const float4*)&g_w1s[0][0];
        float4* db = (float4*)(sm + OFF_B);
        for (int i = tid; i < 2176; i += THREADS) db[i] = s0[i];
    }
    __syncthreads();

    // ======== act: silu(h_s[:,:128]) -> A-fragments in registers ==========
    uint32_t afrag[32];
    #pragma unroll
    for (int h = 0; h < 2; ++h) {
        float acc[8][4] = {};
        gemm8<4>(acc, aOff, bOff + h * 128, PB * 2);
        #pragma unroll
        for (int t = 0; t < 8; t += 2) {       // kb_local = t/2
            int kb = h * 4 + (t >> 1);
            float a0 = INV * acc[t][0],     a1 = INV * acc[t][1];
            float a2 = INV * acc[t][2],     a3 = INV * acc[t][3];
            float a4 = INV * acc[t + 1][0], a5 = INV * acc[t + 1][1];
            float a6 = INV * acc[t + 1][2], a7 = INV * acc[t + 1][3];
            a0 *= sigf(a0); a1 *= sigf(a1); a2 *= sigf(a2); a3 *= sigf(a3);
            a4 *= sigf(a4); a5 *= sigf(a5); a6 *= sigf(a6); a7 *= sigf(a7);
            afrag[4 * kb + 0] = h2u(__floats2half2_rn(a0, a1));
            afrag[4 * kb + 1] = h2u(__floats2half2_rn(a2, a3));
            afrag[4 * kb + 2] = h2u(__floats2half2_rn(a4, a5));
            afrag[4 * kb + 3] = h2u(__floats2half2_rn(a6, a7));
        }
    }
    __syncthreads();               // B (w1s h0) consumed; A (x_s) dead

    // ======== L2-s from registers || B <- w1v ========
    {
        float acc2[2][4] = {};
        gemm8_regA(acc2, afrag, bOffS, PW * 2);
        long gr0 = tile0 + row0, gr1 = gr0 + 8;
        if (gr0 < N) {
            *(float2*)&out[gr0 * 64 + cpair]     = make_float2(INV * acc2[0][0], INV * acc2[0][1]);
            *(float2*)&out[gr0 * 64 + cpair + 8] = make_float2(INV * acc2[1][0], INV * acc2[1][1]);
        }
        if (gr1 < N) {
            *(float2*)&out[gr1 * 64 + cpair]     = make_float2(INV * acc2[0][2], INV * acc2[0][3]);
            *(float2*)&out[gr1 * 64 + cpair + 8] = make_float2(INV * acc2[1][2], INV * acc2[1][3]);
        }
        const float4* sv = (const float4*)g_w1v;
        float4* db = (float4*)(sm + OFF_B);
        for (int i = tid; i < 2176; i += THREADS) db[i] = sv[i];
    }
    __syncthreads();               // B = w1v ready; no more CTA barriers below

    // ======== per-channel: stage v_c -> G1-v -> gate -> L2-v (warp-local) ==
    #pragma unroll
    for (int c = 0; c < 3; ++c) {
        // stage v channel into A (each warp writes only its own 16 rows)
        {
            int n = tid >> 1, half = tid & 1;
            long row = tile0 + n;
            bool ok = row < N;
            const float4* vp = (const float4*)(x + row * DIN + 128 + half * 192);
            char* dst = sm + OFF_A + (n * PA + half * 64) * 2;
            #pragma unroll
            for (int blk = 0; blk < 4; ++blk) {
                float f[48];
                #pragma unroll
                for (int q = 0; q < 12; ++q) {
                    float4 t = ok ? vp[blk * 12 + q] : make_float4(0.f, 0.f, 0.f, 0.f);
                    f[4 * q] = t.x; f[4 * q + 1] = t.y;
                    f[4 * q + 2] = t.z; f[4 * q + 3] = t.w;
                }
                uint32_t u[8];
                #pragma unroll
                for (int p = 0; p < 8; ++p)
                    u[p] = h2u(__floats2half2_rn(f[(2 * p) * 3 + c],
                                                 f[(2 * p + 1) * 3 + c]));
                *(uint4*)(dst + blk * 32)      = make_uint4(u[0], u[1], u[2], u[3]);
                *(uint4*)(dst + blk * 32 + 16) = make_uint4(u[4], u[5], u[6], u[7]);
            }
        }
        __syncwarp();

        // G1-v (two halves) -> gate-multiply -> A-fragments in registers
        #pragma unroll
        for (int h = 0; h < 2; ++h) {
            float acc[8][4] = {};
            gemm8<4>(acc, aOff, bOff + h * 128, PB * 2);
            #pragma unroll
            for (int t = 0; t < 8; t += 2) {
                int kb = h * 4 + (t >> 1);
                int col = h * 64 + 8 * t + cpair;
                float2 g00 = __half22float2(*(__half2*)(sm + OFF_GATE + (row0 * PG + col) * 2));
                float2 g01 = __half22float2(*(__half2*)(sm + OFF_GATE + ((row0 + 8) * PG + col) * 2));
                float2 g10 = __half22float2(*(__half2*)(sm + OFF_GATE + (row0 * PG + col + 8) * 2));
                float2 g11 = __half22float2(*(__half2*)(sm + OFF_GATE + ((row0 + 8) * PG + col + 8) * 2));
                float a0 = INV * acc[t][0] * g00.x,     a1 = INV * acc[t][1] * g00.y;
                float a2 = INV * acc[t][2] * g01.x,     a3 = INV * acc[t][3] * g01.y;
                float a4 = INV * acc[t + 1][0] * g10.x, a5 = INV * acc[t + 1][1] * g10.y;
                float a6 = INV * acc[t + 1][2] * g11.x, a7 = INV * acc[t + 1][3] * g11.y;
                afrag[4 * kb + 0] = h2u(__floats2half2_rn(a0, a1));
                afrag[4 * kb + 1] = h2u(__floats2half2_rn(a2, a3));
                afrag[4 * kb + 2] = h2u(__floats2half2_rn(a4, a5));
                afrag[4 * kb + 3] = h2u(__floats2half2_rn(a6, a7));
            }
        }

        // L2-v from registers
        {
            float acc2[2][4] = {};
            gemm8_regA(acc2, afrag, bOffV, PW * 2);
            long gr0 = tile0 + row0, gr1 = gr0 + 8;
            if (gr0 < N) {
                float* op = out + gr0 * 64 + 16 + c;
                op[(cpair) * 3]     = INV * acc2[0][0];
                op[(cpair + 1) * 3] = INV * acc2[0][1];
                op[(cpair + 8) * 3] = INV * acc2[1][0];
                op[(cpair + 9) * 3] = INV * acc2[1][1];
            }
            if (gr1 < N) {
                float* op = out + gr1 * 64 + 16 + c;
                op[(cpair) * 3]     = INV * acc2[0][2];
                op[(cpair + 1) * 3] = INV * acc2[0][3];
                op[(cpair + 8) * 3] = INV * acc2[1][2];
                op[(cpair + 9) * 3] = INV * acc2[1][3];
            }
        }
        __syncwarp();   // A readers done before next channel's staging
    }
}

// ---------------------------------------------------------------- launch
extern "C" void kernel_launch(void* const* d_in, const int* in_sizes, int n_in,
                              void* d_out, int out_size) {
    const float* x   = (const float*)d_in[0];
    const float* w1s = (const float*)d_in[1];
    const float* w1v = (const float*)d_in[2];
    const float* w2s = (const float*)d_in[3];
    const float* w2v = (const float*)d_in[4];
    float* out = (float*)d_out;

    const int N = in_sizes[0] / DIN;

    prep<<<64, 256>>>(w1s, w1v, w2s, w2v);

    cudaFuncSetAttribute(nlro, cudaFuncAttributeMaxDynamicSharedMemorySize,
                         SMEM_BYTES);
    const int grid = (N + TILE_M - 1) / TILE_M;
    nlro<<<grid, THREADS, SMEM_BYTES>>>(x, out, N);
}

// round 6
// speedup vs baseline: 2.4259x; 1.0889x over previous
#include <cuda_runtime.h>
#include <cuda_fp16.h>
#include <cstdint>

// Fused NonLinearReadoutLayer via mma.sync.m16n8k16 (fp16 in, fp32 accum).
// Gates live in registers (C-frag == gate-consumer frag); v staged 2-pass into
// two A buffers; out_v accumulated in regs, written as contiguous float2 runs.

#define DIN     512
#define TILE_M  128
#define THREADS 256

#define PA  136   // halves
#define PB  136
#define PW2 40    // combined w2s (cols 0-15) | w2v (cols 16-31)

#define OFF_A0 0u          // x_s -> v_c0 -> v_c2          34816
#define OFF_A1 34816u      // v_c1                         34816
#define OFF_B  69632u      // w1s h1 -> w1s h0 -> w1v      34816
#define OFF_W2 104448u     // combined W2 image            10240
#define SMEM_BYTES 114688u

__device__ __align__(16) __half g_w1s[2][128 * PB];
__device__ __align__(16) __half g_w1v[128 * PB];
__device__ __align__(16) __half g_w2[128 * PW2];

// ---------------------------------------------------------------- helpers
__device__ __forceinline__ uint32_t smem_u32(const void* p) {
    uint32_t a;
    asm("{ .reg .u64 t; cvta.to.shared.u64 t, %1; cvt.u32.u64 %0, t; }"
        : "=r"(a) : "l"(p));
    return a;
}
__device__ __forceinline__ uint32_t h2u(__half2 h) {
    return *reinterpret_cast<uint32_t*>(&h);
}
__device__ __forceinline__ float sigf(float x) {
    return __fdividef(1.0f, 1.0f + __expf(-x));
}
__device__ __forceinline__ void ldsm4(uint32_t* r, uint32_t addr) {
    asm volatile("ldmatrix.sync.aligned.m8n8.x4.shared.b16 {%0,%1,%2,%3}, [%4];"
                 : "=r"(r[0]), "=r"(r[1]), "=r"(r[2]), "=r"(r[3]) : "r"(addr));
}
__device__ __forceinline__ void ldsm4t(uint32_t* r, uint32_t addr) {
    asm volatile("ldmatrix.sync.aligned.m8n8.x4.trans.shared.b16 {%0,%1,%2,%3}, [%4];"
                 : "=r"(r[0]), "=r"(r[1]), "=r"(r[2]), "=r"(r[3]) : "r"(addr));
}
__device__ __forceinline__ void mma16816(float* c, const uint32_t* a, const uint32_t* b) {
    asm volatile(
        "mma.sync.aligned.m16n8k16.row.col.f32.f16.f16.f32 "
        "{%0,%1,%2,%3}, {%4,%5,%6,%7}, {%8,%9}, {%0,%1,%2,%3};"
        : "+f"(c[0]), "+f"(c[1]), "+f"(c[2]), "+f"(c[3])
        : "r"(a[0]), "r"(a[1]), "r"(a[2]), "r"(a[3]), "r"(b[0]), "r"(b[1]));
}
template <int NG>
__device__ __forceinline__ void gemm8(float (*acc)[4], uint32_t aAddr,
                                      uint32_t bAddr, uint32_t pbB) {
    #pragma unroll
    for (int k = 0; k < 8; ++k) {
        uint32_t a[4];
        ldsm4(a, aAddr + k * 32);
        #pragma unroll
        for (int g = 0; g < NG; ++g) {
            uint32_t b[4];
            ldsm4t(b, bAddr + k * 16 * pbB + g * 32);
            mma16816(acc[2 * g],     a, b);
            mma16816(acc[2 * g + 1], a, b + 2);
        }
    }
}
__device__ __forceinline__ void gemm8_regA(float (*acc)[4], const uint32_t* afrag,
                                           uint32_t bAddr, uint32_t pbB) {
    #pragma unroll
    for (int kb = 0; kb < 8; ++kb) {
        uint32_t b[4];
        ldsm4t(b, bAddr + kb * 16 * pbB);
        mma16816(acc[0], afrag + 4 * kb, b);
        mma16816(acc[1], afrag + 4 * kb, b + 2);
    }
}

// ---------------------------------------------------------------- prep
__global__ void prep(const float* __restrict__ w1s, const float* __restrict__ w1v,
                     const float* __restrict__ w2s, const float* __restrict__ w2v) {
    int idx = blockIdx.x * blockDim.x + threadIdx.x;
    int stride = gridDim.x * blockDim.x;
    for (int i = idx; i < 2 * 128 * 128; i += stride) {
        int h = i >> 14, k = (i >> 7) & 127, n = i & 127;
        g_w1s[h][k * PB + n] = __float2half_rn(w1s[k * 256 + h * 128 + n]);
    }
    for (int i = idx; i < 128 * 128; i += stride)
        g_w1v[(i >> 7) * PB + (i & 127)] = __float2half_rn(w1v[i]);
    for (int i = idx; i < 128 * 16; i += stride) {
        int k = i >> 4, n = i & 15;
        g_w2[k * PW2 + n]      = __float2half_rn(w2s[i]);
        g_w2[k * PW2 + 16 + n] = __float2half_rn(w2v[i]);
    }
}

// ---------------------------------------------------------------- main
__global__ void __launch_bounds__(THREADS, 2)
nlro(const float* __restrict__ x, float* __restrict__ out, int N) {
    extern __shared__ char sm[];
    const uint32_t smb = smem_u32(sm);
    const int tid = threadIdx.x, lane = tid & 31, wid = tid >> 5;
    const long tile0 = (long)blockIdx.x * TILE_M;
    const float INV = 0.08838834764831845f;

    const int row0 = wid * 16 + (lane >> 2);
    const int cpair = 2 * (lane & 3);
    const int l16 = lane & 15, lhi = lane >> 4;

    const uint32_t aOff0 = smb + OFF_A0 + ((wid * 16 + l16) * PA + lhi * 8) * 2;
    const uint32_t aOff1 = aOff0 + (OFF_A1 - OFF_A0);
    const uint32_t bOff  = smb + OFF_B + (l16 * PB + lhi * 8) * 2;
    const uint32_t bOffS = smb + OFF_W2 + (l16 * PW2 + lhi * 8) * 2;
    const uint32_t bOffV = bOffS + 32;   // +16 half cols

    // ======== phase 0: stage x_s; B <- w1s[1]; W2 image ========
    {
        int n = tid >> 1, kg = tid & 1;
        long row = tile0 + n;
        bool ok = row < N;
        const float4* xp = (const float4*)(x + row * DIN + kg * 64);
        char* dst = sm + OFF_A0 + (n * PA + kg * 64) * 2;
        #pragma unroll
        for (int t = 0; t < 8; ++t) {
            float4 v0 = ok ? xp[2 * t]     : make_float4(0.f, 0.f, 0.f, 0.f);
            float4 v1 = ok ? xp[2 * t + 1] : make_float4(0.f, 0.f, 0.f, 0.f);
            uint4 u;
            u.x = h2u(__floats2half2_rn(v0.x, v0.y));
            u.y = h2u(__floats2half2_rn(v0.z, v0.w));
            u.z = h2u(__floats2half2_rn(v1.x, v1.y));
            u.w = h2u(__floats2half2_rn(v1.z, v1.w));
            *(uint4*)(dst + t * 16) = u;
        }
        const float4* s1 = (const float4*)&g_w1s[1][0];
        float4* db = (float4*)(sm + OFF_B);
        for (int i = tid; i < 2176; i += THREADS) db[i] = s1[i];
        const float4* s2 = (const float4*)g_w2;
        float4* d2 = (float4*)(sm + OFF_W2);
        for (int i = tid; i < 640; i += THREADS) d2[i] = s2[i];
    }
    __syncthreads();

    // ======== gates: sigmoid(h_s[:,128:]) -> registers ========
    uint32_t gfa[16], gfb[16];
    #pragma unroll
    for (int h = 0; h < 2; ++h) {
        float acc[8][4] = {};
        gemm8<4>(acc, aOff0, bOff + h * 128, PB * 2);
        #pragma unroll
        for (int t = 0; t < 8; ++t) {
            gfa[h * 8 + t] = h2u(__floats2half2_rn(sigf(INV * acc[t][0]),
                                                   sigf(INV * acc[t][1])));
            gfb[h * 8 + t] = h2u(__floats2half2_rn(sigf(INV * acc[t][2]),
                                                   sigf(INV * acc[t][3])));
        }
    }
    __syncthreads();               // B (w1s h1) consumed
    {
        const float4* s0 = (const float4*)&g_w1s[0][0];
        float4* db = (float4*)(sm + OFF_B);
        for (int i = tid; i < 2176; i += THREADS) db[i] = s0[i];
    }
    __syncthreads();

    // ======== act: silu(h_s[:,:128]) -> A-fragments in registers ========
    uint32_t afrag[32];
    #pragma unroll
    for (int h = 0; h < 2; ++h) {
        float acc[8][4] = {};
        gemm8<4>(acc, aOff0, bOff + h * 128, PB * 2);
        #pragma unroll
        for (int t = 0; t < 8; t += 2) {
            int kb = h * 4 + (t >> 1);
            float a0 = INV * acc[t][0],     a1 = INV * acc[t][1];
            float a2 = INV * acc[t][2],     a3 = INV * acc[t][3];
            float a4 = INV * acc[t + 1][0], a5 = INV * acc[t + 1][1];
            float a6 = INV * acc[t + 1][2], a7 = INV * acc[t + 1][3];
            a0 *= sigf(a0); a1 *= sigf(a1); a2 *= sigf(a2); a3 *= sigf(a3);
            a4 *= sigf(a4); a5 *= sigf(a5); a6 *= sigf(a6); a7 *= sigf(a7);
            afrag[4 * kb + 0] = h2u(__floats2half2_rn(a0, a1));
            afrag[4 * kb + 1] = h2u(__floats2half2_rn(a2, a3));
            afrag[4 * kb + 2] = h2u(__floats2half2_rn(a4, a5));
            afrag[4 * kb + 3] = h2u(__floats2half2_rn(a6, a7));
        }
    }

    // ======== L2-s from registers; write out_s ========
    {
        float acc2[2][4] = {};
        gemm8_regA(acc2, afrag, bOffS, PW2 * 2);
        long gr0 = tile0 + row0, gr1 = gr0 + 8;
        if (gr0 < N) {
            *(float2*)&out[gr0 * 64 + cpair]     = make_float2(INV * acc2[0][0], INV * acc2[0][1]);
            *(float2*)&out[gr0 * 64 + cpair + 8] = make_float2(INV * acc2[1][0], INV * acc2[1][1]);
        }
        if (gr1 < N) {
            *(float2*)&out[gr1 * 64 + cpair]     = make_float2(INV * acc2[0][2], INV * acc2[0][3]);
            *(float2*)&out[gr1 * 64 + cpair + 8] = make_float2(INV * acc2[1][2], INV * acc2[1][3]);
        }
    }
    __syncthreads();               // all warps done with w1s h0 and x_s (A0)

    // ======== B <- w1v || stage v channels 0,1 (one pass) ========
    {
        const float4* sv = (const float4*)g_w1v;
        float4* db = (float4*)(sm + OFF_B);
        for (int i = tid; i < 2176; i += THREADS) db[i] = sv[i];

        int n = tid >> 1, half = tid & 1;
        long row = tile0 + n;
        bool ok = row < N;
        const float4* vp = (const float4*)(x + row * DIN + 128 + half * 192);
        char* d0 = sm + OFF_A0 + (n * PA + half * 64) * 2;
        char* d1 = sm + OFF_A1 + (n * PA + half * 64) * 2;
        #pragma unroll
        for (int blk = 0; blk < 4; ++blk) {
            float f[48];
            #pragma unroll
            for (int q = 0; q < 12; ++q) {
                float4 t = ok ? vp[blk * 12 + q] : make_float4(0.f, 0.f, 0.f, 0.f);
                f[4 * q] = t.x; f[4 * q + 1] = t.y;
                f[4 * q + 2] = t.z; f[4 * q + 3] = t.w;
            }
            uint32_t u0[8], u1[8];
            #pragma unroll
            for (int p = 0; p < 8; ++p) {
                u0[p] = h2u(__floats2half2_rn(f[(2 * p) * 3 + 0], f[(2 * p + 1) * 3 + 0]));
                u1[p] = h2u(__floats2half2_rn(f[(2 * p) * 3 + 1], f[(2 * p + 1) * 3 + 1]));
            }
            *(uint4*)(d0 + blk * 32)      = make_uint4(u0[0], u0[1], u0[2], u0[3]);
            *(uint4*)(d0 + blk * 32 + 16) = make_uint4(u0[4], u0[5], u0[6], u0[7]);
            *(uint4*)(d1 + blk * 32)      = make_uint4(u1[0], u1[1], u1[2], u1[3]);
            *(uint4*)(d1 + blk * 32 + 16) = make_uint4(u1[4], u1[5], u1[6], u1[7]);
        }
    }
    __syncthreads();               // B=w1v ready; last CTA barrier

    // ======== per-channel: G1-v -> gate (regs) -> L2-v (warp-local) ========
    float vout[24];                // [r][g][k01][c] = ((r*2+g)*2+k)*3+c
    #define VOUT(r, g, k, c) ((((r) * 2 + (g)) * 2 + (k)) * 3 + (c))
    #pragma unroll
    for (int c = 0; c < 3; ++c) {
        if (c == 2) {              // stage channel 2 into A0 (warp-local)
            __syncwarp();
            int n = tid >> 1, half = tid & 1;
            long row = tile0 + n;
            bool ok = row < N;
            const float4* vp = (const float4*)(x + row * DIN + 128 + half * 192);
            char* d0 = sm + OFF_A0 + (n * PA + half * 64) * 2;
            #pragma unroll
            for (int blk = 0; blk < 4; ++blk) {
                float f[48];
                #pragma unroll
                for (int q = 0; q < 12; ++q) {
                    float4 t = ok ? vp[blk * 12 + q] : make_float4(0.f, 0.f, 0.f, 0.f);
                    f[4 * q] = t.x; f[4 * q + 1] = t.y;
                    f[4 * q + 2] = t.z; f[4 * q + 3] = t.w;
                }
                uint32_t u[8];
                #pragma unroll
                for (int p = 0; p < 8; ++p)
                    u[p] = h2u(__floats2half2_rn(f[(2 * p) * 3 + 2], f[(2 * p + 1) * 3 + 2]));
                *(uint4*)(d0 + blk * 32)      = make_uint4(u[0], u[1], u[2], u[3]);
                *(uint4*)(d0 + blk * 32 + 16) = make_uint4(u[4], u[5], u[6], u[7]);
            }
            __syncwarp();
        }
        const uint32_t aOffC = (c == 1) ? aOff1 : aOff0;

        // G1-v (two halves) -> gate-multiply (register gates) -> afrag
        #pragma unroll
        for (int h = 0; h < 2; ++h) {
            float acc[8][4] = {};
            gemm8<4>(acc, aOffC, bOff + h * 128, PB * 2);
            #pragma unroll
            for (int t = 0; t < 8; t += 2) {
                int kb = h * 4 + (t >> 1);
                float2 g00 = __half22float2(*(__half2*)&gfa[h * 8 + t]);
                float2 g01 = __half22float2(*(__half2*)&gfb[h * 8 + t]);
                float2 g10 = __half22float2(*(__half2*)&gfa[h * 8 + t + 1]);
                float2 g11 = __half22float2(*(__half2*)&gfb[h * 8 + t + 1]);
                float a0 = INV * acc[t][0] * g00.x,     a1 = INV * acc[t][1] * g00.y;
                float a2 = INV * acc[t][2] * g01.x,     a3 = INV * acc[t][3] * g01.y;
                float a4 = INV * acc[t + 1][0] * g10.x, a5 = INV * acc[t + 1][1] * g10.y;
                float a6 = INV * acc[t + 1][2] * g11.x, a7 = INV * acc[t + 1][3] * g11.y;
                afrag[4 * kb + 0] = h2u(__floats2half2_rn(a0, a1));
                afrag[4 * kb + 1] = h2u(__floats2half2_rn(a2, a3));
                afrag[4 * kb + 2] = h2u(__floats2half2_rn(a4, a5));
                afrag[4 * kb + 3] = h2u(__floats2half2_rn(a6, a7));
            }
        }

        // L2-v from registers -> vout registers
        {
            float acc2[2][4] = {};
            gemm8_regA(acc2, afrag, bOffV, PW2 * 2);
            vout[VOUT(0, 0, 0, c)] = INV * acc2[0][0];
            vout[VOUT(0, 0, 1, c)] = INV * acc2[0][1];
            vout[VOUT(1, 0, 0, c)] = INV * acc2[0][2];
            vout[VOUT(1, 0, 1, c)] = INV * acc2[0][3];
            vout[VOUT(0, 1, 0, c)] = INV * acc2[1][0];
            vout[VOUT(0, 1, 1, c)] = INV * acc2[1][1];
            vout[VOUT(1, 1, 0, c)] = INV * acc2[1][2];
            vout[VOUT(1, 1, 1, c)] = INV * acc2[1][3];
        }
    }

    // ======== write out_v: contiguous float2 runs ========
    #pragma unroll
    for (int r = 0; r < 2; ++r) {
        long gr = tile0 + row0 + r * 8;
        if (gr < N) {
            float* op = out + gr * 64 + 16;
            #pragma unroll
            for (int g = 0; g < 2; ++g) {
                int kb = cpair + 8 * g;
                float* q = op + kb * 3;
                *(float2*)(q + 0) = make_float2(vout[VOUT(r, g, 0, 0)], vout[VOUT(r, g, 0, 1)]);
                *(float2*)(q + 2) = make_float2(vout[VOUT(r, g, 0, 2)], vout[VOUT(r, g, 1, 0)]);
                *(float2*)(q + 4) = make_float2(vout[VOUT(r, g, 1, 1)], vout[VOUT(r, g, 1, 2)]);
            }
        }
    }
    #undef VOUT
}

// ---------------------------------------------------------------- launch
extern "C" void kernel_launch(void* const* d_in, const int* in_sizes, int n_in,
                              void* d_out, int out_size) {
    const float* x   = (const float*)d_in[0];
    const float* w1s = (const float*)d_in[1];
    const float* w1v = (const float*)d_in[2];
    const float* w2s = (const float*)d_in[3];
    const float* w2v = (const float*)d_in[4];
    float* out = (float*)d_out;

    const int N = in_sizes[0] / DIN;

    prep<<<64, 256>>>(w1s, w1v, w2s, w2v);

    cudaFuncSetAttribute(nlro, cudaFuncAttributeMaxDynamicSharedMemorySize,
                         SMEM_BYTES);
    const int grid = (N + TILE_M - 1) / TILE_M;
    nlro<<<grid, THREADS, SMEM_BYTES>>>(x, out, N);
}

// round 7
// speedup vs baseline: 4.3697x; 1.8012x over previous
#include <cuda_runtime.h>
#include <cuda_fp16.h>
#include <cstdint>

// Fused NonLinearReadoutLayer via mma.sync.m16n8k16 (fp16 in, fp32 accum).
// Round 7: prep kernel deinterleaves/converts x into tile-shaped fp16 planes;
// main kernel staging = coalesced bulk copies; both w1s halves resident;
// A-fragments hoisted to registers; 3 CTA barriers total.

#define DIN     512
#define TILE_M  128
#define THREADS 256
#define MAX_TILES 1564

#define PA  136   // halves (row pitch; 272B = odd 16B multiple -> ldsm conflict-free)
#define PB  136
#define PW2 40    // combined w2s (cols 0-15) | w2v (cols 16-31)

#define OFF_A0 0u          // x_s -> v channels (rotating, warp-local rows)
#define OFF_R1 34816u      // w1s[0] -> w1v
#define OFF_R2 69632u      // w1s[1]
#define OFF_W2 104448u
#define SMEM_BYTES 114688u

// ---- prepared images ----
__device__ __align__(16) __half g_w1s[2][128 * PB];
__device__ __align__(16) __half g_w1v[128 * PB];
__device__ __align__(16) __half g_w2[128 * PW2];
__device__ __align__(16) __half g_xs[(long)MAX_TILES * 128 * PA];
__device__ __align__(16) __half g_xv[(long)MAX_TILES * 3 * 128 * PA];

// ---------------------------------------------------------------- helpers
__device__ __forceinline__ uint32_t smem_u32(const void* p) {
    uint32_t a;
    asm("{ .reg .u64 t; cvta.to.shared.u64 t, %1; cvt.u32.u64 %0, t; }"
        : "=r"(a) : "l"(p));
    return a;
}
__device__ __forceinline__ uint32_t h2u(__half2 h) {
    return *reinterpret_cast<uint32_t*>(&h);
}
__device__ __forceinline__ float sigf(float x) {
    return __fdividef(1.0f, 1.0f + __expf(-x));
}
__device__ __forceinline__ void ldsm4(uint32_t* r, uint32_t addr) {
    asm volatile("ldmatrix.sync.aligned.m8n8.x4.shared.b16 {%0,%1,%2,%3}, [%4];"
                 : "=r"(r[0]), "=r"(r[1]), "=r"(r[2]), "=r"(r[3]) : "r"(addr));
}
__device__ __forceinline__ void ldsm4t(uint32_t* r, uint32_t addr) {
    asm volatile("ldmatrix.sync.aligned.m8n8.x4.trans.shared.b16 {%0,%1,%2,%3}, [%4];"
                 : "=r"(r[0]), "=r"(r[1]), "=r"(r[2]), "=r"(r[3]) : "r"(addr));
}
__device__ __forceinline__ void mma16816(float* c, const uint32_t* a, const uint32_t* b) {
    asm volatile(
        "mma.sync.aligned.m16n8k16.row.col.f32.f16.f16.f32 "
        "{%0,%1,%2,%3}, {%4,%5,%6,%7}, {%8,%9}, {%0,%1,%2,%3};"
        : "+f"(c[0]), "+f"(c[1]), "+f"(c[2]), "+f"(c[3])
        : "r"(a[0]), "r"(a[1]), "r"(a[2]), "r"(a[3]), "r"(b[0]), "r"(b[1]));
}
// load all 8 k16 A-fragments (m16 x k128) into registers
__device__ __forceinline__ void ldsmA(uint32_t* af, uint32_t aAddr) {
    #pragma unroll
    for (int k = 0; k < 8; ++k) ldsm4(af + 4 * k, aAddr + k * 32);
}
// GEMM with A in regs, B from smem, 4 n16 groups (64 cols)
__device__ __forceinline__ void gemm_rA4(float (*acc)[4], const uint32_t* af,
                                         uint32_t bAddr, uint32_t pbB) {
    #pragma unroll
    for (int k = 0; k < 8; ++k) {
        #pragma unroll
        for (int g = 0; g < 4; ++g) {
            uint32_t b[4];
            ldsm4t(b, bAddr + k * 16 * pbB + g * 32);
            mma16816(acc[2 * g],     af + 4 * k, b);
            mma16816(acc[2 * g + 1], af + 4 * k, b + 2);
        }
    }
}
// GEMM with A in regs, B from smem, 1 n16 group (L2 layers)
__device__ __forceinline__ void gemm_rA1(float (*acc)[4], const uint32_t* af,
                                         uint32_t bAddr, uint32_t pbB) {
    #pragma unroll
    for (int k = 0; k < 8; ++k) {
        uint32_t b[4];
        ldsm4t(b, bAddr + k * 16 * pbB);
        mma16816(acc[0], af + 4 * k, b);
        mma16816(acc[1], af + 4 * k, b + 2);
    }
}

// ---------------------------------------------------------------- prep: weights
__global__ void prep_w(const float* __restrict__ w1s, const float* __restrict__ w1v,
                       const float* __restrict__ w2s, const float* __restrict__ w2v) {
    int idx = blockIdx.x * blockDim.x + threadIdx.x;
    int stride = gridDim.x * blockDim.x;
    for (int i = idx; i < 2 * 128 * 128; i += stride) {
        int h = i >> 14, k = (i >> 7) & 127, n = i & 127;
        g_w1s[h][k * PB + n] = __float2half_rn(w1s[k * 256 + h * 128 + n]);
    }
    for (int i = idx; i < 128 * 128; i += stride)
        g_w1v[(i >> 7) * PB + (i & 127)] = __float2half_rn(w1v[i]);
    for (int i = idx; i < 128 * 16; i += stride) {
        int k = i >> 4, n = i & 15;
        g_w2[k * PW2 + n]      = __float2half_rn(w2s[i]);
        g_w2[k * PW2 + 16 + n] = __float2half_rn(w2v[i]);
    }
}

// ---------------------------------------------------------------- prep: x planes
// one CTA per 128-row tile; builds g_xs[tile] and g_xv[tile][c] (zero-padded rows)
__global__ void __launch_bounds__(256)
prep_x(const float* __restrict__ x, int N) {
    const int tile = blockIdx.x;
    const int tid = threadIdx.x;
    const long tile0 = (long)tile * TILE_M;

    // s part: 1024 units of 16 floats
    #pragma unroll
    for (int it = 0; it < 4; ++it) {
        int u = it * 256 + tid;
        int row = u >> 3, seg = u & 7;
        long grow = tile0 + row;
        bool ok = grow < N;
        const float4* src = (const float4*)(x + grow * DIN + seg * 16);
        float4 f0 = ok ? src[0] : make_float4(0, 0, 0, 0);
        float4 f1 = ok ? src[1] : make_float4(0, 0, 0, 0);
        float4 f2 = ok ? src[2] : make_float4(0, 0, 0, 0);
        float4 f3 = ok ? src[3] : make_float4(0, 0, 0, 0);
        uint4 a, b;
        a.x = h2u(__floats2half2_rn(f0.x, f0.y));
        a.y = h2u(__floats2half2_rn(f0.z, f0.w));
        a.z = h2u(__floats2half2_rn(f1.x, f1.y));
        a.w = h2u(__floats2half2_rn(f1.z, f1.w));
        b.x = h2u(__floats2half2_rn(f2.x, f2.y));
        b.y = h2u(__floats2half2_rn(f2.z, f2.w));
        b.z = h2u(__floats2half2_rn(f3.x, f3.y));
        b.w = h2u(__floats2half2_rn(f3.z, f3.w));
        uint4* dst = (uint4*)&g_xs[((long)tile * 128 + row) * PA + seg * 16];
        dst[0] = a;
        dst[1] = b;
    }

    // v part: 4096 units of 12 floats (4 m-triples)
    #pragma unroll
    for (int it = 0; it < 16; ++it) {
        int u = it * 256 + tid;
        int row = u >> 5, seg = u & 31;
        long grow = tile0 + row;
        bool ok = grow < N;
        const float4* src = (const float4*)(x + grow * DIN + 128 + seg * 12);
        float4 f0 = ok ? src[0] : make_float4(0, 0, 0, 0);
        float4 f1 = ok ? src[1] : make_float4(0, 0, 0, 0);
        float4 f2 = ok ? src[2] : make_float4(0, 0, 0, 0);
        float f[12] = {f0.x, f0.y, f0.z, f0.w, f1.x, f1.y, f1.z, f1.w,
                       f2.x, f2.y, f2.z, f2.w};
        #pragma unroll
        for (int c = 0; c < 3; ++c) {
            uint2 w;
            w.x = h2u(__floats2half2_rn(f[c],     f[3 + c]));
            w.y = h2u(__floats2half2_rn(f[6 + c], f[9 + c]));
            *(uint2*)&g_xv[(((long)tile * 3 + c) * 128 + row) * PA + seg * 4] = w;
        }
    }
}

// ---------------------------------------------------------------- main
__global__ void __launch_bounds__(THREADS, 2)
nlro(float* __restrict__ out, int N) {
    extern __shared__ char sm[];
    const uint32_t smb = smem_u32(sm);
    const int tid = threadIdx.x, lane = tid & 31, wid = tid >> 5;
    const int tile = blockIdx.x;
    const long tile0 = (long)tile * TILE_M;
    const float INV = 0.08838834764831845f;

    const int row0 = wid * 16 + (lane >> 2);
    const int cpair = 2 * (lane & 3);
    const int l16 = lane & 15, lhi = lane >> 4;

    const uint32_t aOff  = smb + OFF_A0 + ((wid * 16 + l16) * PA + lhi * 8) * 2;
    const uint32_t bR1   = smb + OFF_R1 + (l16 * PB + lhi * 8) * 2;
    const uint32_t bR2   = smb + OFF_R2 + (l16 * PB + lhi * 8) * 2;
    const uint32_t bOffS = smb + OFF_W2 + (l16 * PW2 + lhi * 8) * 2;
    const uint32_t bOffV = bOffS + 32;

    // ======== phase 0: bulk copies (all coalesced float4) ========
    {
        const float4* xs = (const float4*)&g_xs[(long)tile * 128 * PA];
        const float4* s0 = (const float4*)&g_w1s[0][0];
        const float4* s1 = (const float4*)&g_w1s[1][0];
        float4* dA = (float4*)(sm + OFF_A0);
        float4* d1 = (float4*)(sm + OFF_R1);
        float4* d2 = (float4*)(sm + OFF_R2);
        for (int i = tid; i < 2176; i += THREADS) {
            dA[i] = xs[i]; d1[i] = s0[i]; d2[i] = s1[i];
        }
        const float4* s2 = (const float4*)g_w2;
        float4* dw = (float4*)(sm + OFF_W2);
        for (int i = tid; i < 640; i += THREADS) dw[i] = s2[i];
    }
    __syncthreads();   // barrier 1

    // A-fragments of x_s (reused for gates AND act)
    uint32_t af[32];
    ldsmA(af, aOff);

    // ======== gates: sigmoid(h_s[:,128:]) -> registers ========
    uint32_t gfa[16], gfb[16];
    #pragma unroll
    for (int h = 0; h < 2; ++h) {
        float acc[8][4] = {};
        gemm_rA4(acc, af, bR2 + h * 128, PB * 2);
        #pragma unroll
        for (int t = 0; t < 8; ++t) {
            gfa[h * 8 + t] = h2u(__floats2half2_rn(sigf(INV * acc[t][0]),
                                                   sigf(INV * acc[t][1])));
            gfb[h * 8 + t] = h2u(__floats2half2_rn(sigf(INV * acc[t][2]),
                                                   sigf(INV * acc[t][3])));
        }
    }

    // ======== act: silu(h_s[:,:128]) -> A-fragments in registers ========
    uint32_t afrag[32];
    #pragma unroll
    for (int h = 0; h < 2; ++h) {
        float acc[8][4] = {};
        gemm_rA4(acc, af, bR1 + h * 128, PB * 2);
        #pragma unroll
        for (int t = 0; t < 8; t += 2) {
            int kb = h * 4 + (t >> 1);
            float a0 = INV * acc[t][0],     a1 = INV * acc[t][1];
            float a2 = INV * acc[t][2],     a3 = INV * acc[t][3];
            float a4 = INV * acc[t + 1][0], a5 = INV * acc[t + 1][1];
            float a6 = INV * acc[t + 1][2], a7 = INV * acc[t + 1][3];
            a0 *= sigf(a0); a1 *= sigf(a1); a2 *= sigf(a2); a3 *= sigf(a3);
            a4 *= sigf(a4); a5 *= sigf(a5); a6 *= sigf(a6); a7 *= sigf(a7);
            afrag[4 * kb + 0] = h2u(__floats2half2_rn(a0, a1));
            afrag[4 * kb + 1] = h2u(__floats2half2_rn(a2, a3));
            afrag[4 * kb + 2] = h2u(__floats2half2_rn(a4, a5));
            afrag[4 * kb + 3] = h2u(__floats2half2_rn(a6, a7));
        }
    }
    __syncthreads();   // barrier 2: R1 + A0 free to overwrite

    // ======== copies (w1v CTA-wide, v_c0 warp-local) then L2-s ========
    {
        const float4* sv = (const float4*)g_w1v;
        float4* d1 = (float4*)(sm + OFF_R1);
        for (int i = tid; i < 2176; i += THREADS) d1[i] = sv[i];

        const float4* srcv = (const float4*)&g_xv[(((long)tile * 3 + 0) * 128 + wid * 16) * PA];
        float4* dA = (float4*)(sm + OFF_A0 + wid * 16 * PA * 2);
        for (int i = lane; i < 272; i += 32) dA[i] = srcv[i];
    }
    {
        float acc2[2][4] = {};
        gemm_rA1(acc2, afrag, bOffS, PW2 * 2);
        long gr0 = tile0 + row0, gr1 = gr0 + 8;
        if (gr0 < N) {
            *(float2*)&out[gr0 * 64 + cpair]     = make_float2(INV * acc2[0][0], INV * acc2[0][1]);
            *(float2*)&out[gr0 * 64 + cpair + 8] = make_float2(INV * acc2[1][0], INV * acc2[1][1]);
        }
        if (gr1 < N) {
            *(float2*)&out[gr1 * 64 + cpair]     = make_float2(INV * acc2[0][2], INV * acc2[0][3]);
            *(float2*)&out[gr1 * 64 + cpair + 8] = make_float2(INV * acc2[1][2], INV * acc2[1][3]);
        }
    }
    __syncthreads();   // barrier 3 (last): w1v ready; channel loop is warp-local

    // ======== per-channel: G1-v -> gate (regs) -> L2-v ========
    float vout[24];
    #define VOUT(r, g, k, c) ((((r) * 2 + (g)) * 2 + (k)) * 3 + (c))
    #pragma unroll
    for (int c = 0; c < 3; ++c) {
        if (c > 0) {   // warp-local copy of channel c into A0 rows
            __syncwarp();
            const float4* srcv =
                (const float4*)&g_xv[(((long)tile * 3 + c) * 128 + wid * 16) * PA];
            float4* dA = (float4*)(sm + OFF_A0 + wid * 16 * PA * 2);
            for (int i = lane; i < 272; i += 32) dA[i] = srcv[i];
            __syncwarp();
        }
        ldsmA(af, aOff);

        #pragma unroll
        for (int h = 0; h < 2; ++h) {
            float acc[8][4] = {};
            gemm_rA4(acc, af, bR1 + h * 128, PB * 2);
            #pragma unroll
            for (int t = 0; t < 8; t += 2) {
                int kb = h * 4 + (t >> 1);
                float2 g00 = __half22float2(*(__half2*)&gfa[h * 8 + t]);
                float2 g01 = __half22float2(*(__half2*)&gfb[h * 8 + t]);
                float2 g10 = __half22float2(*(__half2*)&gfa[h * 8 + t + 1]);
                float2 g11 = __half22float2(*(__half2*)&gfb[h * 8 + t + 1]);
                float a0 = INV * acc[t][0] * g00.x,     a1 = INV * acc[t][1] * g00.y;
                float a2 = INV * acc[t][2] * g01.x,     a3 = INV * acc[t][3] * g01.y;
                float a4 = INV * acc[t + 1][0] * g10.x, a5 = INV * acc[t + 1][1] * g10.y;
                float a6 = INV * acc[t + 1][2] * g11.x, a7 = INV * acc[t + 1][3] * g11.y;
                afrag[4 * kb + 0] = h2u(__floats2half2_rn(a0, a1));
                afrag[4 * kb + 1] = h2u(__floats2half2_rn(a2, a3));
                afrag[4 * kb + 2] = h2u(__floats2half2_rn(a4, a5));
                afrag[4 * kb + 3] = h2u(__floats2half2_rn(a6, a7));
            }
        }
        {
            float acc2[2][4] = {};
            gemm_rA1(acc2, afrag, bOffV, PW2 * 2);
            vout[VOUT(0, 0, 0, c)] = INV * acc2[0][0];
            vout[VOUT(0, 0, 1, c)] = INV * acc2[0][1];
            vout[VOUT(1, 0, 0, c)] = INV * acc2[0][2];
            vout[VOUT(1, 0, 1, c)] = INV * acc2[0][3];
            vout[VOUT(0, 1, 0, c)] = INV * acc2[1][0];
            vout[VOUT(0, 1, 1, c)] = INV * acc2[1][1];
            vout[VOUT(1, 1, 0, c)] = INV * acc2[1][2];
            vout[VOUT(1, 1, 1, c)] = INV * acc2[1][3];
        }
    }

    // ======== write out_v: contiguous float2 runs ========
    #pragma unroll
    for (int r = 0; r < 2; ++r) {
        long gr = tile0 + row0 + r * 8;
        if (gr < N) {
            float* op = out + gr * 64 + 16;
            #pragma unroll
            for (int g = 0; g < 2; ++g) {
                int kb = cpair + 8 * g;
                float* q = op + kb * 3;
                *(float2*)(q + 0) = make_float2(vout[VOUT(r, g, 0, 0)], vout[VOUT(r, g, 0, 1)]);
                *(float2*)(q + 2) = make_float2(vout[VOUT(r, g, 0, 2)], vout[VOUT(r, g, 1, 0)]);
                *(float2*)(q + 4) = make_float2(vout[VOUT(r, g, 1, 1)], vout[VOUT(r, g, 1, 2)]);
            }
        }
    }
    #undef VOUT
}

// ---------------------------------------------------------------- launch
extern "C" void kernel_launch(void* const* d_in, const int* in_sizes, int n_in,
                              void* d_out, int out_size) {
    const float* x   = (const float*)d_in[0];
    const float* w1s = (const float*)d_in[1];
    const float* w1v = (const float*)d_in[2];
    const float* w2s = (const float*)d_in[3];
    const float* w2v = (const float*)d_in[4];
    float* out = (float*)d_out;

    const int N = in_sizes[0] / DIN;
    const int tiles = (N + TILE_M - 1) / TILE_M;

    prep_w<<<64, 256>>>(w1s, w1v, w2s, w2v);
    prep_x<<<tiles, 256>>>(x, N);

    cudaFuncSetAttribute(nlro, cudaFuncAttributeMaxDynamicSharedMemorySize,
                         SMEM_BYTES);
    nlro<<<tiles, THREADS, SMEM_BYTES>>>(out, N);
}

// round 8
// speedup vs baseline: 5.6944x; 1.3032x over previous
#include <cuda_runtime.h>
#include <cuda_fp16.h>
#include <cstdint>

// Fused NonLinearReadoutLayer via mma.sync.m16n8k16 (fp16 in, fp32 accum).
// Round 8: cp.async-pipelined staging; all copies overlapped with compute.

#define DIN     512
#define TILE_M  128
#define THREADS 256
#define MAX_TILES 1564

#define PA  136   // halves
#define PB  136
#define PW2 40

#define OFF_A0 0u          // x_s -> ch0 -> ch2
#define OFF_R1 34816u      // w1s[0] -> ch1
#define OFF_R2 69632u      // w1s[1] -> w1v
#define OFF_W2 104448u
#define SMEM_BYTES 114688u

__device__ __align__(16) __half g_w1s[2][128 * PB];
__device__ __align__(16) __half g_w1v[128 * PB];
__device__ __align__(16) __half g_w2[128 * PW2];
__device__ __align__(16) __half g_xs[(long)MAX_TILES * 128 * PA];
__device__ __align__(16) __half g_xv[(long)MAX_TILES * 3 * 128 * PA];

// ---------------------------------------------------------------- helpers
__device__ __forceinline__ uint32_t smem_u32(const void* p) {
    uint32_t a;
    asm("{ .reg .u64 t; cvta.to.shared.u64 t, %1; cvt.u32.u64 %0, t; }"
        : "=r"(a) : "l"(p));
    return a;
}
__device__ __forceinline__ uint32_t h2u(__half2 h) {
    return *reinterpret_cast<uint32_t*>(&h);
}
__device__ __forceinline__ float sigf(float x) {
    return __fdividef(1.0f, 1.0f + __expf(-x));
}
#define CP16(d, s) \
    asm volatile("cp.async.cg.shared.global [%0], [%1], 16;" \
                 :: "r"(d), "l"(s))
#define CP_COMMIT() asm volatile("cp.async.commit_group;" ::: "memory")
#define CP_WAIT(n)  asm volatile("cp.async.wait_group %0;" :: "n"(n) : "memory")

__device__ __forceinline__ void cp_bulk(uint32_t dst, const void* src, int n16,
                                        int tid) {
    const char* s = (const char*)src;
    for (int i = tid; i < n16; i += THREADS) CP16(dst + i * 16, s + (long)i * 16);
}
__device__ __forceinline__ void cp_warp(uint32_t dst, const void* src, int lane) {
    const char* s = (const char*)src;
    #pragma unroll
    for (int i = lane; i < 272; i += 32) CP16(dst + i * 16, s + (long)i * 16);
}

__device__ __forceinline__ void ldsm4(uint32_t* r, uint32_t addr) {
    asm volatile("ldmatrix.sync.aligned.m8n8.x4.shared.b16 {%0,%1,%2,%3}, [%4];"
                 : "=r"(r[0]), "=r"(r[1]), "=r"(r[2]), "=r"(r[3]) : "r"(addr));
}
__device__ __forceinline__ void ldsm4t(uint32_t* r, uint32_t addr) {
    asm volatile("ldmatrix.sync.aligned.m8n8.x4.trans.shared.b16 {%0,%1,%2,%3}, [%4];"
                 : "=r"(r[0]), "=r"(r[1]), "=r"(r[2]), "=r"(r[3]) : "r"(addr));
}
__device__ __forceinline__ void mma16816(float* c, const uint32_t* a, const uint32_t* b) {
    asm volatile(
        "mma.sync.aligned.m16n8k16.row.col.f32.f16.f16.f32 "
        "{%0,%1,%2,%3}, {%4,%5,%6,%7}, {%8,%9}, {%0,%1,%2,%3};"
        : "+f"(c[0]), "+f"(c[1]), "+f"(c[2]), "+f"(c[3])
        : "r"(a[0]), "r"(a[1]), "r"(a[2]), "r"(a[3]), "r"(b[0]), "r"(b[1]));
}
__device__ __forceinline__ void ldsmA(uint32_t* af, uint32_t aAddr) {
    #pragma unroll
    for (int k = 0; k < 8; ++k) ldsm4(af + 4 * k, aAddr + k * 32);
}
__device__ __forceinline__ void gemm_rA4(float (*acc)[4], const uint32_t* af,
                                         uint32_t bAddr, uint32_t pbB) {
    #pragma unroll
    for (int k = 0; k < 8; ++k) {
        #pragma unroll
        for (int g = 0; g < 4; ++g) {
            uint32_t b[4];
            ldsm4t(b, bAddr + k * 16 * pbB + g * 32);
            mma16816(acc[2 * g],     af + 4 * k, b);
            mma16816(acc[2 * g + 1], af + 4 * k, b + 2);
        }
    }
}
__device__ __forceinline__ void gemm_rA1(float (*acc)[4], const uint32_t* af,
                                         uint32_t bAddr, uint32_t pbB) {
    #pragma unroll
    for (int k = 0; k < 8; ++k) {
        uint32_t b[4];
        ldsm4t(b, bAddr + k * 16 * pbB);
        mma16816(acc[0], af + 4 * k, b);
        mma16816(acc[1], af + 4 * k, b + 2);
    }
}

// ---------------------------------------------------------------- prep (fused)
__global__ void __launch_bounds__(256)
prep_x(const float* __restrict__ x, int N,
       const float* __restrict__ w1s, const float* __restrict__ w1v,
       const float* __restrict__ w2s, const float* __restrict__ w2v) {
    const int tile = blockIdx.x;
    const int tid = threadIdx.x;
    const long tile0 = (long)tile * TILE_M;

    // weight prep spread over first 64 CTAs
    if (tile < 64) {
        int idx = tile * 256 + tid;
        int stride = 64 * 256;
        for (int i = idx; i < 2 * 128 * 128; i += stride) {
            int h = i >> 14, k = (i >> 7) & 127, n = i & 127;
            g_w1s[h][k * PB + n] = __float2half_rn(w1s[k * 256 + h * 128 + n]);
        }
        for (int i = idx; i < 128 * 128; i += stride)
            g_w1v[(i >> 7) * PB + (i & 127)] = __float2half_rn(w1v[i]);
        for (int i = idx; i < 128 * 16; i += stride) {
            int k = i >> 4, n = i & 15;
            g_w2[k * PW2 + n]      = __float2half_rn(w2s[i]);
            g_w2[k * PW2 + 16 + n] = __float2half_rn(w2v[i]);
        }
    }

    // s part
    #pragma unroll
    for (int it = 0; it < 4; ++it) {
        int u = it * 256 + tid;
        int row = u >> 3, seg = u & 7;
        long grow = tile0 + row;
        bool ok = grow < N;
        const float4* src = (const float4*)(x + grow * DIN + seg * 16);
        float4 f0 = ok ? src[0] : make_float4(0, 0, 0, 0);
        float4 f1 = ok ? src[1] : make_float4(0, 0, 0, 0);
        float4 f2 = ok ? src[2] : make_float4(0, 0, 0, 0);
        float4 f3 = ok ? src[3] : make_float4(0, 0, 0, 0);
        uint4 a, b;
        a.x = h2u(__floats2half2_rn(f0.x, f0.y));
        a.y = h2u(__floats2half2_rn(f0.z, f0.w));
        a.z = h2u(__floats2half2_rn(f1.x, f1.y));
        a.w = h2u(__floats2half2_rn(f1.z, f1.w));
        b.x = h2u(__floats2half2_rn(f2.x, f2.y));
        b.y = h2u(__floats2half2_rn(f2.z, f2.w));
        b.z = h2u(__floats2half2_rn(f3.x, f3.y));
        b.w = h2u(__floats2half2_rn(f3.z, f3.w));
        uint4* dst = (uint4*)&g_xs[((long)tile * 128 + row) * PA + seg * 16];
        dst[0] = a;
        dst[1] = b;
    }
    // v part
    #pragma unroll
    for (int it = 0; it < 16; ++it) {
        int u = it * 256 + tid;
        int row = u >> 5, seg = u & 31;
        long grow = tile0 + row;
        bool ok = grow < N;
        const float4* src = (const float4*)(x + grow * DIN + 128 + seg * 12);
        float4 f0 = ok ? src[0] : make_float4(0, 0, 0, 0);
        float4 f1 = ok ? src[1] : make_float4(0, 0, 0, 0);
        float4 f2 = ok ? src[2] : make_float4(0, 0, 0, 0);
        float f[12] = {f0.x, f0.y, f0.z, f0.w, f1.x, f1.y, f1.z, f1.w,
                       f2.x, f2.y, f2.z, f2.w};
        #pragma unroll
        for (int c = 0; c < 3; ++c) {
            uint2 w;
            w.x = h2u(__floats2half2_rn(f[c],     f[3 + c]));
            w.y = h2u(__floats2half2_rn(f[6 + c], f[9 + c]));
            *(uint2*)&g_xv[(((long)tile * 3 + c) * 128 + row) * PA + seg * 4] = w;
        }
    }
}

// ---------------------------------------------------------------- main
__global__ void __launch_bounds__(THREADS, 2)
nlro(float* __restrict__ out, int N) {
    extern __shared__ char sm[];
    const uint32_t smb = smem_u32(sm);
    const int tid = threadIdx.x, lane = tid & 31, wid = tid >> 5;
    const int tile = blockIdx.x;
    const long tile0 = (long)tile * TILE_M;
    const float INV = 0.08838834764831845f;

    const int row0 = wid * 16 + (lane >> 2);
    const int cpair = 2 * (lane & 3);
    const int l16 = lane & 15, lhi = lane >> 4;

    const uint32_t aOff  = smb + OFF_A0 + ((wid * 16 + l16) * PA + lhi * 8) * 2;
    const uint32_t bR1   = smb + OFF_R1 + (l16 * PB + lhi * 8) * 2;
    const uint32_t bR2   = smb + OFF_R2 + (l16 * PB + lhi * 8) * 2;
    const uint32_t bOffS = smb + OFF_W2 + (l16 * PW2 + lhi * 8) * 2;
    const uint32_t bOffV = bOffS + 32;

    const __half* xsP  = &g_xs[(long)tile * 128 * PA];
    const __half* xv0  = &g_xv[((long)tile * 3 + 0) * 128 * PA];
    const __half* xv1  = &g_xv[((long)tile * 3 + 1) * 128 * PA];
    const __half* xv2  = &g_xv[((long)tile * 3 + 2) * 128 * PA];
    const uint32_t warpA = smb + OFF_A0 + wid * 16 * PA * 2;
    const uint32_t warpR1 = smb + OFF_R1 + wid * 16 * PA * 2;
    const long wrows = (long)wid * 16 * PA;

    // ---- G0: A0 (x_s) + R2 (w1s[1]);  G1: R1 (w1s[0]);  G2: W2 ----
    cp_bulk(smb + OFF_A0, xsP, 2176, tid);
    cp_bulk(smb + OFF_R2, &g_w1s[1][0], 2176, tid);
    CP_COMMIT();
    cp_bulk(smb + OFF_R1, &g_w1s[0][0], 2176, tid);
    CP_COMMIT();
    cp_bulk(smb + OFF_W2, g_w2, 640, tid);
    CP_COMMIT();

    CP_WAIT(2);            // G0 done: A0 + R2
    __syncthreads();       // b1

    uint32_t af[32];
    ldsmA(af, aOff);       // A0 (warp rows) -> regs; A0 free for this warp

    cp_warp(warpA, xv0 + wrows, lane);   // G3: ch0 -> A0 (warp-local)
    CP_COMMIT();

    // ======== gates: sigmoid(h_s[:,128:]) -> registers (uses R2) ========
    uint32_t gfa[16], gfb[16];
    #pragma unroll
    for (int h = 0; h < 2; ++h) {
        float acc[8][4] = {};
        gemm_rA4(acc, af, bR2 + h * 128, PB * 2);
        #pragma unroll
        for (int t = 0; t < 8; ++t) {
            gfa[h * 8 + t] = h2u(__floats2half2_rn(sigf(INV * acc[t][0]),
                                                   sigf(INV * acc[t][1])));
            gfb[h * 8 + t] = h2u(__floats2half2_rn(sigf(INV * acc[t][2]),
                                                   sigf(INV * acc[t][3])));
        }
    }

    CP_WAIT(2);            // G1 done: R1 (w1s[0])
    __syncthreads();       // b2: R1 visible CTA-wide; R2 released by all warps

    cp_bulk(smb + OFF_R2, g_w1v, 2176, tid);   // G4: w1v -> R2
    CP_COMMIT();

    // ======== act: silu(h_s[:,:128]) -> A-fragments (uses R1) ========
    uint32_t afrag[32];
    #pragma unroll
    for (int h = 0; h < 2; ++h) {
        float acc[8][4] = {};
        gemm_rA4(acc, af, bR1 + h * 128, PB * 2);
        #pragma unroll
        for (int t = 0; t < 8; t += 2) {
            int kb = h * 4 + (t >> 1);
            float a0 = INV * acc[t][0],     a1 = INV * acc[t][1];
            float a2 = INV * acc[t][2],     a3 = INV * acc[t][3];
            float a4 = INV * acc[t + 1][0], a5 = INV * acc[t + 1][1];
            float a6 = INV * acc[t + 1][2], a7 = INV * acc[t + 1][3];
            a0 *= sigf(a0); a1 *= sigf(a1); a2 *= sigf(a2); a3 *= sigf(a3);
            a4 *= sigf(a4); a5 *= sigf(a5); a6 *= sigf(a6); a7 *= sigf(a7);
            afrag[4 * kb + 0] = h2u(__floats2half2_rn(a0, a1));
            afrag[4 * kb + 1] = h2u(__floats2half2_rn(a2, a3));
            afrag[4 * kb + 2] = h2u(__floats2half2_rn(a4, a5));
            afrag[4 * kb + 3] = h2u(__floats2half2_rn(a6, a7));
        }
    }

    CP_WAIT(2);            // G2 done: own W2 parts
    __syncthreads();       // b3: W2 visible CTA-wide; R1 released by all warps

    cp_warp(warpR1, xv1 + wrows, lane);  // G5: ch1 -> R1 (warp-local)
    CP_COMMIT();

    // ======== L2-s from registers; write out_s (uses W2) ========
    {
        float acc2[2][4] = {};
        gemm_rA1(acc2, afrag, bOffS, PW2 * 2);
        long gr0 = tile0 + row0, gr1 = gr0 + 8;
        if (gr0 < N) {
            *(float2*)&out[gr0 * 64 + cpair]     = make_float2(INV * acc2[0][0], INV * acc2[0][1]);
            *(float2*)&out[gr0 * 64 + cpair + 8] = make_float2(INV * acc2[1][0], INV * acc2[1][1]);
        }
        if (gr1 < N) {
            *(float2*)&out[gr1 * 64 + cpair]     = make_float2(INV * acc2[0][2], INV * acc2[0][3]);
            *(float2*)&out[gr1 * 64 + cpair + 8] = make_float2(INV * acc2[1][2], INV * acc2[1][3]);
        }
    }

    CP_WAIT(1);            // G3 (ch0) + G4 (w1v) done
    __syncthreads();       // b4 (last): w1v visible CTA-wide

    // ======== per-channel: G1-v -> gate (regs) -> L2-v (warp-local) ========
    float vout[24];
    #define VOUT(r, g, k, c) ((((r) * 2 + (g)) * 2 + (k)) * 3 + (c))
    #pragma unroll
    for (int c = 0; c < 3; ++c) {
        if (c == 1) { CP_WAIT(1); __syncwarp(); }   // G5 (ch1) done
        if (c == 2) { CP_WAIT(0); __syncwarp(); }   // G6 (ch2) done
        const uint32_t aOffC = (c == 1) ? (aOff + (OFF_R1 - OFF_A0)) : aOff;
        ldsmA(af, aOffC);
        if (c == 0) {                               // prefetch ch2 into A0
            cp_warp(warpA, xv2 + wrows, lane);      // G6
            CP_COMMIT();
        }

        #pragma unroll
        for (int h = 0; h < 2; ++h) {
            float acc[8][4] = {};
            gemm_rA4(acc, af, bR2 + h * 128, PB * 2);
            #pragma unroll
            for (int t = 0; t < 8; t += 2) {
                int kb = h * 4 + (t >> 1);
                float2 g00 = __half22float2(*(__half2*)&gfa[h * 8 + t]);
                float2 g01 = __half22float2(*(__half2*)&gfb[h * 8 + t]);
                float2 g10 = __half22float2(*(__half2*)&gfa[h * 8 + t + 1]);
                float2 g11 = __half22float2(*(__half2*)&gfb[h * 8 + t + 1]);
                float a0 = INV * acc[t][0] * g00.x,     a1 = INV * acc[t][1] * g00.y;
                float a2 = INV * acc[t][2] * g01.x,     a3 = INV * acc[t][3] * g01.y;
                float a4 = INV * acc[t + 1][0] * g10.x, a5 = INV * acc[t + 1][1] * g10.y;
                float a6 = INV * acc[t + 1][2] * g11.x, a7 = INV * acc[t + 1][3] * g11.y;
                afrag[4 * kb + 0] = h2u(__floats2half2_rn(a0, a1));
                afrag[4 * kb + 1] = h2u(__floats2half2_rn(a2, a3));
                afrag[4 * kb + 2] = h2u(__floats2half2_rn(a4, a5));
                afrag[4 * kb + 3] = h2u(__floats2half2_rn(a6, a7));
            }
        }
        {
            float acc2[2][4] = {};
            gemm_rA1(acc2, afrag, bOffV, PW2 * 2);
            vout[VOUT(0, 0, 0, c)] = INV * acc2[0][0];
            vout[VOUT(0, 0, 1, c)] = INV * acc2[0][1];
            vout[VOUT(1, 0, 0, c)] = INV * acc2[0][2];
            vout[VOUT(1, 0, 1, c)] = INV * acc2[0][3];
            vout[VOUT(0, 1, 0, c)] = INV * acc2[1][0];
            vout[VOUT(0, 1, 1, c)] = INV * acc2[1][1];
            vout[VOUT(1, 1, 0, c)] = INV * acc2[1][2];
            vout[VOUT(1, 1, 1, c)] = INV * acc2[1][3];
        }
    }

    // ======== write out_v ========
    #pragma unroll
    for (int r = 0; r < 2; ++r) {
        long gr = tile0 + row0 + r * 8;
        if (gr < N) {
            float* op = out + gr * 64 + 16;
            #pragma unroll
            for (int g = 0; g < 2; ++g) {
                int kb = cpair + 8 * g;
                float* q = op + kb * 3;
                *(float2*)(q + 0) = make_float2(vout[VOUT(r, g, 0, 0)], vout[VOUT(r, g, 0, 1)]);
                *(float2*)(q + 2) = make_float2(vout[VOUT(r, g, 0, 2)], vout[VOUT(r, g, 1, 0)]);
                *(float2*)(q + 4) = make_float2(vout[VOUT(r, g, 1, 1)], vout[VOUT(r, g, 1, 2)]);
            }
        }
    }
    #undef VOUT
}

// ---------------------------------------------------------------- launch
extern "C" void kernel_launch(void* const* d_in, const int* in_sizes, int n_in,
                              void* d_out, int out_size) {
    const float* x   = (const float*)d_in[0];
    const float* w1s = (const float*)d_in[1];
    const float* w1v = (const float*)d_in[2];
    const float* w2s = (const float*)d_in[3];
    const float* w2v = (const float*)d_in[4];
    float* out = (float*)d_out;

    const int N = in_sizes[0] / DIN;
    const int tiles = (N + TILE_M - 1) / TILE_M;

    prep_x<<<tiles, 256>>>(x, N, w1s, w1v, w2s, w2v);

    cudaFuncSetAttribute(nlro, cudaFuncAttributeMaxDynamicSharedMemorySize,
                         SMEM_BYTES);
    nlro<<<tiles, THREADS, SMEM_BYTES>>>(out, N);
}